// round 2
// baseline (speedup 1.0000x reference)
#include <cuda_runtime.h>

#define N_NODES 50000
#define N_EDGES 800000
#define CIN 128
#define COUT 128

// Scratch (allocation-free: __device__ globals)
__device__ int   g_is64;                 // 1 if edge_index buffer is int64
__device__ int   g_deg[N_NODES];
__device__ int   g_off[N_NODES + 1];
__device__ int   g_cur[N_NODES];
__device__ int   g_scol[N_EDGES];
__device__ float g_xt[(size_t)N_NODES * COUT];

// ---------------------------------------------------------------------------
// KD: detect edge_index dtype. If the buffer is int64, every 8-byte word is a
// valid node id in [0, N_NODES). If it is int32, an 8-byte read packs two
// indices and is ~never < 50000 (high word nonzero w.p. 1 - 2e-5 per elem).
__global__ void k_detect(const void* ei_raw) {
    if (threadIdx.x == 0 && blockIdx.x == 0) {
        const long long* p = (const long long*)ei_raw;
        int ok = 1;
        for (int i = 0; i < 64; i++) {
            long long v = p[i];
            if (v < 0 || v >= N_NODES) { ok = 0; break; }
        }
        g_is64 = ok;
    }
}

__device__ __forceinline__ int load_edge(const void* ei_raw, long long idx) {
    if (g_is64) return (int)((const long long*)ei_raw)[idx];
    return ((const int*)ei_raw)[idx];
}

// ---------------------------------------------------------------------------
// K0: zero degree counters
__global__ void k_zero() {
    int i = blockIdx.x * blockDim.x + threadIdx.x;
    if (i < N_NODES) g_deg[i] = 0;
}

// K1: count degree per destination row
__global__ void k_count(const void* __restrict__ ei) {
    int e = blockIdx.x * blockDim.x + threadIdx.x;
    if (e < N_EDGES) {
        int r = load_edge(ei, e);
        if (r >= 0 && r < N_NODES) atomicAdd(&g_deg[r], 1);
    }
}

// K2: single-block exclusive scan over degrees -> offsets + cursor copy
__global__ void k_scan() {
    __shared__ int ssum[1024];
    const int CH = (N_NODES + 1023) / 1024;  // 49
    int tid = threadIdx.x;
    int base = tid * CH;

    int s = 0;
    for (int i = 0; i < CH; i++) {
        int idx = base + i;
        if (idx < N_NODES) s += g_deg[idx];
    }
    ssum[tid] = s;
    __syncthreads();

    // Hillis-Steele inclusive scan over 1024 partials
    for (int d = 1; d < 1024; d <<= 1) {
        int v = (tid >= d) ? ssum[tid - d] : 0;
        __syncthreads();
        ssum[tid] += v;
        __syncthreads();
    }

    int run = (tid == 0) ? 0 : ssum[tid - 1];
    for (int i = 0; i < CH; i++) {
        int idx = base + i;
        if (idx < N_NODES) {
            int d = g_deg[idx];
            g_off[idx] = run;
            g_cur[idx] = run;
            run += d;
        }
    }
    if (tid == 1023) g_off[N_NODES] = ssum[1023];  // == N_EDGES
}

// K3: scatter source columns into CSR adjacency
__global__ void k_scatter(const void* __restrict__ ei) {
    int e = blockIdx.x * blockDim.x + threadIdx.x;
    if (e < N_EDGES) {
        int r = load_edge(ei, e);
        int c = load_edge(ei, (long long)e + N_EDGES);
        if (r >= 0 && r < N_NODES && c >= 0 && c < N_NODES) {
            int p = atomicAdd(&g_cur[r], 1);
            g_scol[p] = c;
        }
    }
}

// ---------------------------------------------------------------------------
// K4: x_t = x @ W^T + b
// Block: 256 threads = 64 out-channels (one half of 128, chosen by blockIdx.y)
//        x 4 node-groups; each thread accumulates 4 nodes -> each W smem read
//        amortized over 16 FMAs (FMA-pipe bound, not LDS bound).
#define NODES_PER_BLOCK 64
__global__ void __launch_bounds__(256) k_linear(const float* __restrict__ x,
                                                const float* __restrict__ W,
                                                const float* __restrict__ b) {
    __shared__ float  Ws[64 * 132];      // [oo][k], pad 132 -> conflict-free float4
    __shared__ float4 xs4[16 * 32];      // 16 nodes x 128 ch (as float4)

    int tid  = threadIdx.x;
    int half = blockIdx.y;               // which 64 output channels
    int oo   = tid & 63;
    int ng   = tid >> 6;                 // node-group 0..3

    // Load W half-tile coalesced: W[(half*64+oo)*128 + k]
    for (int i = tid; i < 64 * 128; i += 256) {
        int woo = i >> 7, k = i & 127;
        Ws[woo * 132 + k] = W[half * 8192 + i];
    }
    float bias = b[half * 64 + oo];

    const float4* x4   = (const float4*)x;
    const float4* Wrow = (const float4*)&Ws[oo * 132];  // 528B aligned
    int nb0 = blockIdx.x * NODES_PER_BLOCK;

    for (int it = 0; it < NODES_PER_BLOCK / 16; it++) {
        int tile0 = nb0 + it * 16;
        __syncthreads();  // protect xs4 reuse (also covers initial Ws load)
        for (int i = tid; i < 16 * 32; i += 256) {
            int nn = i >> 5, k4 = i & 31;
            int node = tile0 + nn;
            xs4[i] = (node < N_NODES) ? x4[(size_t)node * 32 + k4]
                                      : make_float4(0.f, 0.f, 0.f, 0.f);
        }
        __syncthreads();

        float acc0 = 0.f, acc1 = 0.f, acc2 = 0.f, acc3 = 0.f;
        int nbase = ng * 4;
#pragma unroll 8
        for (int k4 = 0; k4 < 32; k4++) {
            float4 w  = Wrow[k4];
            float4 v0 = xs4[(nbase + 0) * 32 + k4];
            float4 v1 = xs4[(nbase + 1) * 32 + k4];
            float4 v2 = xs4[(nbase + 2) * 32 + k4];
            float4 v3 = xs4[(nbase + 3) * 32 + k4];
            acc0 += v0.x * w.x + v0.y * w.y + v0.z * w.z + v0.w * w.w;
            acc1 += v1.x * w.x + v1.y * w.y + v1.z * w.z + v1.w * w.w;
            acc2 += v2.x * w.x + v2.y * w.y + v2.z * w.z + v2.w * w.w;
            acc3 += v3.x * w.x + v3.y * w.y + v3.z * w.z + v3.w * w.w;
        }
        int o = half * 64 + oo;
        int n0 = tile0 + nbase;
        if (n0 + 0 < N_NODES) g_xt[(size_t)(n0 + 0) * 128 + o] = acc0 + bias;
        if (n0 + 1 < N_NODES) g_xt[(size_t)(n0 + 1) * 128 + o] = acc1 + bias;
        if (n0 + 2 < N_NODES) g_xt[(size_t)(n0 + 2) * 128 + o] = acc2 + bias;
        if (n0 + 3 < N_NODES) g_xt[(size_t)(n0 + 3) * 128 + o] = acc3 + bias;
    }
}

// ---------------------------------------------------------------------------
// K5: warp-per-node segmented sum over CSR + fused tanh. No atomics.
__global__ void k_gather(float* __restrict__ out) {
    int gw   = (blockIdx.x * blockDim.x + threadIdx.x) >> 5;  // node id
    int lane = threadIdx.x & 31;
    if (gw >= N_NODES) return;

    int s = g_off[gw];
    int e = g_off[gw + 1];
    const float4* xt4 = (const float4*)g_xt;

    float4 acc = make_float4(0.f, 0.f, 0.f, 0.f);
    int cnext = (s < e) ? __ldg(&g_scol[s]) : 0;
    for (int i = s; i < e; i++) {
        int c = cnext;
        if (i + 1 < e) cnext = __ldg(&g_scol[i + 1]);  // pipeline index load
        float4 v = xt4[(size_t)c * 32 + lane];
        acc.x += v.x; acc.y += v.y; acc.z += v.z; acc.w += v.w;
    }
    float4 r = make_float4(tanhf(acc.x), tanhf(acc.y), tanhf(acc.z), tanhf(acc.w));
    ((float4*)out)[(size_t)gw * 32 + lane] = r;
}

// ---------------------------------------------------------------------------
extern "C" void kernel_launch(void* const* d_in, const int* in_sizes, int n_in,
                              void* d_out, int out_size) {
    const float* x  = (const float*)d_in[0];
    const void*  ei = d_in[1];
    const float* W  = (const float*)d_in[2];
    const float* b  = (const float*)d_in[3];
    float*       out = (float*)d_out;

    k_detect<<<1, 32>>>(ei);
    k_zero<<<(N_NODES + 255) / 256, 256>>>();
    k_count<<<(N_EDGES + 255) / 256, 256>>>(ei);
    k_scan<<<1, 1024>>>();
    k_scatter<<<(N_EDGES + 255) / 256, 256>>>(ei);

    dim3 lgrid((N_NODES + NODES_PER_BLOCK - 1) / NODES_PER_BLOCK, 2);
    k_linear<<<lgrid, 256>>>(x, W, b);

    k_gather<<<(N_NODES * 32 + 255) / 256, 256>>>(out);
}

// round 3
// speedup vs baseline: 1.4999x; 1.4999x over previous
#include <cuda_runtime.h>

#define N_NODES 50000
#define N_EDGES 800000
#define CIN 128
#define COUT 128

#define SCAN_BLOCKS ((N_NODES + 255) / 256)   // 196

// Scratch (allocation-free: __device__ globals)
__device__ int   g_is64;
__device__ int   g_deg[N_NODES];
__device__ int   g_off[N_NODES + 1];
__device__ int   g_cur[N_NODES];
__device__ int   g_part[SCAN_BLOCKS];
__device__ int   g_scol[N_EDGES];
__device__ float g_xt[(size_t)N_NODES * COUT];

// ---------------------------------------------------------------------------
// KD: detect edge_index dtype (int64 layout -> every 8B word in [0, N_NODES)).
__global__ void k_detect(const void* ei_raw) {
    if (threadIdx.x == 0 && blockIdx.x == 0) {
        const long long* p = (const long long*)ei_raw;
        int ok = 1;
        for (int i = 0; i < 64; i++) {
            long long v = p[i];
            if (v < 0 || v >= N_NODES) { ok = 0; break; }
        }
        g_is64 = ok;
    }
}

__device__ __forceinline__ int load_edge(const void* ei_raw, long long idx) {
    if (g_is64) return (int)((const long long*)ei_raw)[idx];
    return ((const int*)ei_raw)[idx];
}

// ---------------------------------------------------------------------------
__global__ void k_zero() {
    int i = blockIdx.x * blockDim.x + threadIdx.x;
    if (i < N_NODES) g_deg[i] = 0;
}

__global__ void k_count(const void* __restrict__ ei) {
    int e = blockIdx.x * blockDim.x + threadIdx.x;
    if (e < N_EDGES) {
        int r = load_edge(ei, e);
        if (r >= 0 && r < N_NODES) atomicAdd(&g_deg[r], 1);
    }
}

// ---------------------------------------------------------------------------
// Multi-block exclusive scan of g_deg -> g_off / g_cur.
// Phase 1: per-block sum of 256 degrees.
__global__ void k_scan1() {
    __shared__ int warpsum[8];
    int i = blockIdx.x * 256 + threadIdx.x;
    int v = (i < N_NODES) ? g_deg[i] : 0;
#pragma unroll
    for (int d = 16; d > 0; d >>= 1) v += __shfl_down_sync(0xffffffffu, v, d);
    if ((threadIdx.x & 31) == 0) warpsum[threadIdx.x >> 5] = v;
    __syncthreads();
    if (threadIdx.x < 8) {
        int s = warpsum[threadIdx.x];
#pragma unroll
        for (int d = 4; d > 0; d >>= 1) s += __shfl_down_sync(0xffu, s, d);
        if (threadIdx.x == 0) g_part[blockIdx.x] = s;
    }
}

// Phase 2: single-block exclusive scan over 196 block partials (tiny).
__global__ void k_scan2() {
    __shared__ int sp[256];
    int tid = threadIdx.x;
    int v = (tid < SCAN_BLOCKS) ? g_part[tid] : 0;
    sp[tid] = v;
    __syncthreads();
#pragma unroll
    for (int d = 1; d < 256; d <<= 1) {
        int u = (tid >= d) ? sp[tid - d] : 0;
        __syncthreads();
        sp[tid] += u;
        __syncthreads();
    }
    if (tid < SCAN_BLOCKS) g_part[tid] = (tid == 0) ? 0 : sp[tid - 1];  // exclusive
    if (tid == 255) g_off[N_NODES] = sp[255];  // == N_EDGES
}

// Phase 3: per-block exclusive scan + block offset -> g_off, g_cur.
__global__ void k_scan3() {
    __shared__ int sv[256];
    int tid = threadIdx.x;
    int i = blockIdx.x * 256 + tid;
    int v = (i < N_NODES) ? g_deg[i] : 0;
    sv[tid] = v;
    __syncthreads();
#pragma unroll
    for (int d = 1; d < 256; d <<= 1) {
        int u = (tid >= d) ? sv[tid - d] : 0;
        __syncthreads();
        sv[tid] += u;
        __syncthreads();
    }
    if (i < N_NODES) {
        int excl = g_part[blockIdx.x] + sv[tid] - v;  // inclusive - self
        g_off[i] = excl;
        g_cur[i] = excl;
    }
}

// ---------------------------------------------------------------------------
__global__ void k_scatter(const void* __restrict__ ei) {
    int e = blockIdx.x * blockDim.x + threadIdx.x;
    if (e < N_EDGES) {
        int r = load_edge(ei, e);
        int c = load_edge(ei, (long long)e + N_EDGES);
        if (r >= 0 && r < N_NODES && c >= 0 && c < N_NODES) {
            int p = atomicAdd(&g_cur[r], 1);
            g_scol[p] = c;
        }
    }
}

// ---------------------------------------------------------------------------
// K4: x_t = x @ W^T + b  (fp32, smem-tiled, FMA-bound)
#define NODES_PER_BLOCK 64
__global__ void __launch_bounds__(256) k_linear(const float* __restrict__ x,
                                                const float* __restrict__ W,
                                                const float* __restrict__ b) {
    __shared__ float  Ws[64 * 132];
    __shared__ float4 xs4[16 * 32];

    int tid  = threadIdx.x;
    int half = blockIdx.y;
    int oo   = tid & 63;
    int ng   = tid >> 6;

    for (int i = tid; i < 64 * 128; i += 256) {
        int woo = i >> 7, k = i & 127;
        Ws[woo * 132 + k] = W[half * 8192 + i];
    }
    float bias = b[half * 64 + oo];

    const float4* x4   = (const float4*)x;
    const float4* Wrow = (const float4*)&Ws[oo * 132];
    int nb0 = blockIdx.x * NODES_PER_BLOCK;

    for (int it = 0; it < NODES_PER_BLOCK / 16; it++) {
        int tile0 = nb0 + it * 16;
        __syncthreads();
        for (int i = tid; i < 16 * 32; i += 256) {
            int nn = i >> 5, k4 = i & 31;
            int node = tile0 + nn;
            xs4[i] = (node < N_NODES) ? x4[(size_t)node * 32 + k4]
                                      : make_float4(0.f, 0.f, 0.f, 0.f);
        }
        __syncthreads();

        float acc0 = 0.f, acc1 = 0.f, acc2 = 0.f, acc3 = 0.f;
        int nbase = ng * 4;
#pragma unroll 8
        for (int k4 = 0; k4 < 32; k4++) {
            float4 w  = Wrow[k4];
            float4 v0 = xs4[(nbase + 0) * 32 + k4];
            float4 v1 = xs4[(nbase + 1) * 32 + k4];
            float4 v2 = xs4[(nbase + 2) * 32 + k4];
            float4 v3 = xs4[(nbase + 3) * 32 + k4];
            acc0 += v0.x * w.x + v0.y * w.y + v0.z * w.z + v0.w * w.w;
            acc1 += v1.x * w.x + v1.y * w.y + v1.z * w.z + v1.w * w.w;
            acc2 += v2.x * w.x + v2.y * w.y + v2.z * w.z + v2.w * w.w;
            acc3 += v3.x * w.x + v3.y * w.y + v3.z * w.z + v3.w * w.w;
        }
        int o = half * 64 + oo;
        int n0 = tile0 + nbase;
        if (n0 + 0 < N_NODES) g_xt[(size_t)(n0 + 0) * 128 + o] = acc0 + bias;
        if (n0 + 1 < N_NODES) g_xt[(size_t)(n0 + 1) * 128 + o] = acc1 + bias;
        if (n0 + 2 < N_NODES) g_xt[(size_t)(n0 + 2) * 128 + o] = acc2 + bias;
        if (n0 + 3 < N_NODES) g_xt[(size_t)(n0 + 3) * 128 + o] = acc3 + bias;
    }
}

// ---------------------------------------------------------------------------
// K5: warp-per-node segmented sum over CSR + fused tanh. No atomics.
__global__ void k_gather(float* __restrict__ out) {
    int gw   = (blockIdx.x * blockDim.x + threadIdx.x) >> 5;
    int lane = threadIdx.x & 31;
    if (gw >= N_NODES) return;

    int s = g_off[gw];
    int e = g_off[gw + 1];
    const float4* xt4 = (const float4*)g_xt;

    float4 acc = make_float4(0.f, 0.f, 0.f, 0.f);
    int cnext = (s < e) ? __ldg(&g_scol[s]) : 0;
    for (int i = s; i < e; i++) {
        int c = cnext;
        if (i + 1 < e) cnext = __ldg(&g_scol[i + 1]);
        float4 v = xt4[(size_t)c * 32 + lane];
        acc.x += v.x; acc.y += v.y; acc.z += v.z; acc.w += v.w;
    }
    float4 r = make_float4(tanhf(acc.x), tanhf(acc.y), tanhf(acc.z), tanhf(acc.w));
    ((float4*)out)[(size_t)gw * 32 + lane] = r;
}

// ---------------------------------------------------------------------------
extern "C" void kernel_launch(void* const* d_in, const int* in_sizes, int n_in,
                              void* d_out, int out_size) {
    const float* x  = (const float*)d_in[0];
    const void*  ei = d_in[1];
    const float* W  = (const float*)d_in[2];
    const float* b  = (const float*)d_in[3];
    float*       out = (float*)d_out;

    k_detect<<<1, 32>>>(ei);
    k_zero<<<(N_NODES + 255) / 256, 256>>>();
    k_count<<<(N_EDGES + 255) / 256, 256>>>(ei);
    k_scan1<<<SCAN_BLOCKS, 256>>>();
    k_scan2<<<1, 256>>>();
    k_scan3<<<SCAN_BLOCKS, 256>>>();
    k_scatter<<<(N_EDGES + 255) / 256, 256>>>(ei);

    dim3 lgrid((N_NODES + NODES_PER_BLOCK - 1) / NODES_PER_BLOCK, 2);
    k_linear<<<lgrid, 256>>>(x, W, b);

    k_gather<<<(N_NODES * 32 + 255) / 256, 256>>>(out);
}

// round 4
// speedup vs baseline: 1.6132x; 1.0756x over previous
#include <cuda_runtime.h>
#include <cuda_fp16.h>

#define N_NODES 50000
#define N_EDGES 800000
#define CIN 128
#define COUT 128

#define SCAN_BLOCKS ((N_NODES + 255) / 256)   // 196

// Scratch (allocation-free: __device__ globals)
__device__ int    g_is64;
__device__ int    g_deg[N_NODES];
__device__ int    g_off[N_NODES + 1];
__device__ int    g_cur[N_NODES];
__device__ int    g_part[SCAN_BLOCKS];
__device__ int    g_scol[N_EDGES];
__device__ __half g_xt[(size_t)N_NODES * COUT];   // fp16 transformed features

// Packed fp32x2 FMA (Blackwell FFMA2 — only reachable via PTX fma.rn.f32x2)
#define FMA_F32X2(d, a, b, c) \
    asm("fma.rn.f32x2 %0, %1, %2, %3;" : "=l"(d) : "l"(a), "l"(b), "l"(c))

__device__ __forceinline__ unsigned long long pack2(float lo, float hi) {
    unsigned long long r;
    asm("mov.b64 %0, {%1, %2};" : "=l"(r) : "f"(lo), "f"(hi));
    return r;
}
__device__ __forceinline__ void unpack2(unsigned long long v, float& lo, float& hi) {
    asm("mov.b64 {%0, %1}, %2;" : "=f"(lo), "=f"(hi) : "l"(v));
}

// ---------------------------------------------------------------------------
// KD: detect edge_index dtype (int64 layout -> every 8B word in [0, N_NODES)).
__global__ void k_detect(const void* ei_raw) {
    if (threadIdx.x == 0 && blockIdx.x == 0) {
        const long long* p = (const long long*)ei_raw;
        int ok = 1;
        for (int i = 0; i < 64; i++) {
            long long v = p[i];
            if (v < 0 || v >= N_NODES) { ok = 0; break; }
        }
        g_is64 = ok;
    }
}

__device__ __forceinline__ int load_edge(const void* ei_raw, long long idx) {
    if (g_is64) return (int)((const long long*)ei_raw)[idx];
    return ((const int*)ei_raw)[idx];
}

// ---------------------------------------------------------------------------
__global__ void k_zero() {
    int i = blockIdx.x * blockDim.x + threadIdx.x;
    if (i < N_NODES) g_deg[i] = 0;
}

__global__ void k_count(const void* __restrict__ ei) {
    int e = blockIdx.x * blockDim.x + threadIdx.x;
    if (e < N_EDGES) {
        int r = load_edge(ei, e);
        if (r >= 0 && r < N_NODES) atomicAdd(&g_deg[r], 1);
    }
}

// ---------------------------------------------------------------------------
// Multi-block exclusive scan of g_deg -> g_off / g_cur.
__global__ void k_scan1() {
    __shared__ int warpsum[8];
    int i = blockIdx.x * 256 + threadIdx.x;
    int v = (i < N_NODES) ? g_deg[i] : 0;
#pragma unroll
    for (int d = 16; d > 0; d >>= 1) v += __shfl_down_sync(0xffffffffu, v, d);
    if ((threadIdx.x & 31) == 0) warpsum[threadIdx.x >> 5] = v;
    __syncthreads();
    if (threadIdx.x < 8) {
        int s = warpsum[threadIdx.x];
#pragma unroll
        for (int d = 4; d > 0; d >>= 1) s += __shfl_down_sync(0xffu, s, d);
        if (threadIdx.x == 0) g_part[blockIdx.x] = s;
    }
}

__global__ void k_scan2() {
    __shared__ int sp[256];
    int tid = threadIdx.x;
    int v = (tid < SCAN_BLOCKS) ? g_part[tid] : 0;
    sp[tid] = v;
    __syncthreads();
#pragma unroll
    for (int d = 1; d < 256; d <<= 1) {
        int u = (tid >= d) ? sp[tid - d] : 0;
        __syncthreads();
        sp[tid] += u;
        __syncthreads();
    }
    if (tid < SCAN_BLOCKS) g_part[tid] = (tid == 0) ? 0 : sp[tid - 1];
    if (tid == 255) g_off[N_NODES] = sp[255];
}

__global__ void k_scan3() {
    __shared__ int sv[256];
    int tid = threadIdx.x;
    int i = blockIdx.x * 256 + tid;
    int v = (i < N_NODES) ? g_deg[i] : 0;
    sv[tid] = v;
    __syncthreads();
#pragma unroll
    for (int d = 1; d < 256; d <<= 1) {
        int u = (tid >= d) ? sv[tid - d] : 0;
        __syncthreads();
        sv[tid] += u;
        __syncthreads();
    }
    if (i < N_NODES) {
        int excl = g_part[blockIdx.x] + sv[tid] - v;
        g_off[i] = excl;
        g_cur[i] = excl;
    }
}

// ---------------------------------------------------------------------------
__global__ void k_scatter(const void* __restrict__ ei) {
    int e = blockIdx.x * blockDim.x + threadIdx.x;
    if (e < N_EDGES) {
        int r = load_edge(ei, e);
        int c = load_edge(ei, (long long)e + N_EDGES);
        if (r >= 0 && r < N_NODES && c >= 0 && c < N_NODES) {
            int p = atomicAdd(&g_cur[r], 1);
            g_scol[p] = c;
        }
    }
}

// ---------------------------------------------------------------------------
// K4: x_t = x @ W^T + b, FFMA2-packed over node pairs, fp16 output.
// Block = 256 thr: 64 out-channels (half selected by blockIdx.y) x 4 groups.
// Tile = 32 nodes = 16 pairs; k processed in two 64-wide halves so
// Ws (64x129 fp32, 33KB) + xs2 (64k x 16 pairs f32x2, 8KB) fit in 48KB.
#define NODES_PER_BLOCK 64
#define TILE_N 32
__global__ void __launch_bounds__(256) k_linear(const float* __restrict__ x,
                                                const float* __restrict__ W,
                                                const float* __restrict__ b) {
    __shared__ float              Ws[64 * 129];      // [oo][k], stride 129 -> conflict-free
    __shared__ unsigned long long xs2[64 * 16];      // [k_local][pair]

    int tid  = threadIdx.x;
    int half = blockIdx.y;
    int oo   = tid & 63;
    int ng   = tid >> 6;                             // 0..3, uniform per warp

    // Load W half-tile: W[(half*64+woo)*128 + k]
    for (int i = tid; i < 64 * 128; i += 256) {
        int woo = i >> 7, k = i & 127;
        Ws[woo * 129 + k] = W[half * 8192 + i];
    }
    float bias = b[half * 64 + oo];

    const float4* x4  = (const float4*)x;
    float*        xsf = (float*)xs2;
    int nb0 = blockIdx.x * NODES_PER_BLOCK;

    for (int t = 0; t < NODES_PER_BLOCK / TILE_N; t++) {
        int tile0 = nb0 + t * TILE_N;

        unsigned long long acc0 = pack2(0.f, 0.f);
        unsigned long long acc1 = acc0, acc2 = acc0, acc3 = acc0;

        for (int kh = 0; kh < 2; kh++) {
            __syncthreads();   // xs2 free for reuse (also covers Ws on 1st pass)
            // Transpose-load 32 nodes x 64 k into xs2 (f32x2 over node pairs).
            // i = k4*32 + nn : STS float idx = klocal*32 + nn -> conflict-free.
            for (int i = tid; i < 16 * 32; i += 256) {
                int k4 = i >> 5, nn = i & 31;
                int node = tile0 + nn;
                float4 v = (node < N_NODES) ? x4[(size_t)node * 32 + kh * 16 + k4]
                                            : make_float4(0.f, 0.f, 0.f, 0.f);
                int base = (k4 * 4) * 32 + nn;
                xsf[base]      = v.x;
                xsf[base + 32] = v.y;
                xsf[base + 64] = v.z;
                xsf[base + 96] = v.w;
            }
            __syncthreads();

            const float* Wrow = &Ws[oo * 129 + kh * 64];
            const ulonglong2* vp = (const ulonglong2*)&xs2[ng * 4];
#pragma unroll 4
            for (int kk = 0; kk < 64; kk++) {
                float w = Wrow[kk];
                unsigned long long w2 = pack2(w, w);
                ulonglong2 va = vp[kk * 8];          // pairs ng*4+0, ng*4+1
                ulonglong2 vb = vp[kk * 8 + 1];      // pairs ng*4+2, ng*4+3
                FMA_F32X2(acc0, va.x, w2, acc0);
                FMA_F32X2(acc1, va.y, w2, acc1);
                FMA_F32X2(acc2, vb.x, w2, acc2);
                FMA_F32X2(acc3, vb.y, w2, acc3);
            }
        }

        // Store: thread owns channel o for 8 nodes (4 pairs).
        int o = half * 64 + oo;
        unsigned long long accs[4] = {acc0, acc1, acc2, acc3};
#pragma unroll
        for (int j = 0; j < 4; j++) {
            float lo, hi;
            unpack2(accs[j], lo, hi);
            int n0 = tile0 + (ng * 4 + j) * 2;
            if (n0 < N_NODES)     g_xt[(size_t)n0 * 128 + o]       = __float2half_rn(lo + bias);
            if (n0 + 1 < N_NODES) g_xt[(size_t)(n0 + 1) * 128 + o] = __float2half_rn(hi + bias);
        }
    }
}

// ---------------------------------------------------------------------------
// K5: warp-per-node segmented sum over CSR (fp16 x_t, fp32 accum) + tanh.
__global__ void k_gather(float* __restrict__ out) {
    int gw   = (blockIdx.x * blockDim.x + threadIdx.x) >> 5;
    int lane = threadIdx.x & 31;
    if (gw >= N_NODES) return;

    int s = g_off[gw];
    int e = g_off[gw + 1];
    const uint2* xt2 = (const uint2*)g_xt;   // 4 halves per lane

    float4 acc = make_float4(0.f, 0.f, 0.f, 0.f);
    int cnext = (s < e) ? __ldg(&g_scol[s]) : 0;
    for (int i = s; i < e; i++) {
        int c = cnext;
        if (i + 1 < e) cnext = __ldg(&g_scol[i + 1]);
        uint2 raw = __ldg(&xt2[(size_t)c * 32 + lane]);
        float2 p0 = __half22float2(*(const __half2*)&raw.x);
        float2 p1 = __half22float2(*(const __half2*)&raw.y);
        acc.x += p0.x; acc.y += p0.y; acc.z += p1.x; acc.w += p1.y;
    }
    float4 r = make_float4(tanhf(acc.x), tanhf(acc.y), tanhf(acc.z), tanhf(acc.w));
    ((float4*)out)[(size_t)gw * 32 + lane] = r;
}

// ---------------------------------------------------------------------------
extern "C" void kernel_launch(void* const* d_in, const int* in_sizes, int n_in,
                              void* d_out, int out_size) {
    const float* x  = (const float*)d_in[0];
    const void*  ei = d_in[1];
    const float* W  = (const float*)d_in[2];
    const float* b  = (const float*)d_in[3];
    float*       out = (float*)d_out;

    k_detect<<<1, 32>>>(ei);
    k_zero<<<(N_NODES + 255) / 256, 256>>>();
    k_count<<<(N_EDGES + 255) / 256, 256>>>(ei);
    k_scan1<<<SCAN_BLOCKS, 256>>>();
    k_scan2<<<1, 256>>>();
    k_scan3<<<SCAN_BLOCKS, 256>>>();
    k_scatter<<<(N_EDGES + 255) / 256, 256>>>(ei);

    dim3 lgrid((N_NODES + NODES_PER_BLOCK - 1) / NODES_PER_BLOCK, 2);
    k_linear<<<lgrid, 256>>>(x, W, b);

    k_gather<<<(N_NODES * 32 + 255) / 256, 256>>>(out);
}

// round 5
// speedup vs baseline: 1.6396x; 1.0163x over previous
#include <cuda_runtime.h>
#include <cuda_fp16.h>

#define N_NODES 50000
#define N_EDGES 800000
#define CIN 128
#define COUT 128

#define SCAN_BLOCKS ((N_NODES + 255) / 256)   // 196

// Scratch (allocation-free: __device__ globals)
__device__ int    g_is64;
__device__ int    g_deg[N_NODES];
__device__ int    g_off[N_NODES + 1];
__device__ int    g_cur[N_NODES];
__device__ int    g_part[SCAN_BLOCKS];
__device__ int    g_scol[N_EDGES];
__device__ __half g_xt[(size_t)N_NODES * COUT];   // fp16 transformed features

// Packed fp32x2 FMA (Blackwell FFMA2 — only reachable via PTX fma.rn.f32x2)
#define FMA_F32X2(d, a, b, c) \
    asm("fma.rn.f32x2 %0, %1, %2, %3;" : "=l"(d) : "l"(a), "l"(b), "l"(c))

__device__ __forceinline__ unsigned long long pack2(float lo, float hi) {
    unsigned long long r;
    asm("mov.b64 %0, {%1, %2};" : "=l"(r) : "f"(lo), "f"(hi));
    return r;
}
__device__ __forceinline__ void unpack2(unsigned long long v, float& lo, float& hi) {
    asm("mov.b64 {%0, %1}, %2;" : "=f"(lo), "=f"(hi) : "l"(v));
}

// ---------------------------------------------------------------------------
// KD: detect edge_index dtype (int64 layout -> every 8B word in [0, N_NODES)).
__global__ void k_detect(const void* ei_raw) {
    if (threadIdx.x == 0 && blockIdx.x == 0) {
        const long long* p = (const long long*)ei_raw;
        int ok = 1;
        for (int i = 0; i < 64; i++) {
            long long v = p[i];
            if (v < 0 || v >= N_NODES) { ok = 0; break; }
        }
        g_is64 = ok;
    }
}

__device__ __forceinline__ int load_edge(const void* ei_raw, long long idx) {
    if (g_is64) return (int)((const long long*)ei_raw)[idx];
    return ((const int*)ei_raw)[idx];
}

// ---------------------------------------------------------------------------
__global__ void k_zero() {
    int i = blockIdx.x * blockDim.x + threadIdx.x;
    if (i < N_NODES) g_deg[i] = 0;
}

__global__ void k_count(const void* __restrict__ ei) {
    int e = blockIdx.x * blockDim.x + threadIdx.x;
    if (e < N_EDGES) {
        int r = load_edge(ei, e);
        if (r >= 0 && r < N_NODES) atomicAdd(&g_deg[r], 1);
    }
}

// ---------------------------------------------------------------------------
// Multi-block exclusive scan of g_deg -> g_off / g_cur.
__global__ void k_scan1() {
    __shared__ int warpsum[8];
    int i = blockIdx.x * 256 + threadIdx.x;
    int v = (i < N_NODES) ? g_deg[i] : 0;
#pragma unroll
    for (int d = 16; d > 0; d >>= 1) v += __shfl_down_sync(0xffffffffu, v, d);
    if ((threadIdx.x & 31) == 0) warpsum[threadIdx.x >> 5] = v;
    __syncthreads();
    if (threadIdx.x < 8) {
        int s = warpsum[threadIdx.x];
#pragma unroll
        for (int d = 4; d > 0; d >>= 1) s += __shfl_down_sync(0xffu, s, d);
        if (threadIdx.x == 0) g_part[blockIdx.x] = s;
    }
}

__global__ void k_scan2() {
    __shared__ int sp[256];
    int tid = threadIdx.x;
    int v = (tid < SCAN_BLOCKS) ? g_part[tid] : 0;
    sp[tid] = v;
    __syncthreads();
#pragma unroll
    for (int d = 1; d < 256; d <<= 1) {
        int u = (tid >= d) ? sp[tid - d] : 0;
        __syncthreads();
        sp[tid] += u;
        __syncthreads();
    }
    if (tid < SCAN_BLOCKS) g_part[tid] = (tid == 0) ? 0 : sp[tid - 1];
    if (tid == 255) g_off[N_NODES] = sp[255];
}

__global__ void k_scan3() {
    __shared__ int sv[256];
    int tid = threadIdx.x;
    int i = blockIdx.x * 256 + tid;
    int v = (i < N_NODES) ? g_deg[i] : 0;
    sv[tid] = v;
    __syncthreads();
#pragma unroll
    for (int d = 1; d < 256; d <<= 1) {
        int u = (tid >= d) ? sv[tid - d] : 0;
        __syncthreads();
        sv[tid] += u;
        __syncthreads();
    }
    if (i < N_NODES) {
        int excl = g_part[blockIdx.x] + sv[tid] - v;
        g_off[i] = excl;
        g_cur[i] = excl;
    }
}

// ---------------------------------------------------------------------------
__global__ void k_scatter(const void* __restrict__ ei) {
    int e = blockIdx.x * blockDim.x + threadIdx.x;
    if (e < N_EDGES) {
        int r = load_edge(ei, e);
        int c = load_edge(ei, (long long)e + N_EDGES);
        if (r >= 0 && r < N_NODES && c >= 0 && c < N_NODES) {
            int p = atomicAdd(&g_cur[r], 1);
            g_scol[p] = c;
        }
    }
}

// ---------------------------------------------------------------------------
// K4: x_t = x @ W^T + b, FFMA2-packed over node pairs, fp16 output.
#define NODES_PER_BLOCK 64
#define TILE_N 32
__global__ void __launch_bounds__(256) k_linear(const float* __restrict__ x,
                                                const float* __restrict__ W,
                                                const float* __restrict__ b) {
    __shared__ float              Ws[64 * 129];      // [oo][k], stride 129 -> conflict-free
    __shared__ unsigned long long xs2[64 * 16];      // [k_local][pair]

    int tid  = threadIdx.x;
    int half = blockIdx.y;
    int oo   = tid & 63;
    int ng   = tid >> 6;                             // 0..3, uniform per warp

    for (int i = tid; i < 64 * 128; i += 256) {
        int woo = i >> 7, k = i & 127;
        Ws[woo * 129 + k] = W[half * 8192 + i];
    }
    float bias = b[half * 64 + oo];

    const float4* x4  = (const float4*)x;
    float*        xsf = (float*)xs2;
    int nb0 = blockIdx.x * NODES_PER_BLOCK;

    for (int t = 0; t < NODES_PER_BLOCK / TILE_N; t++) {
        int tile0 = nb0 + t * TILE_N;

        unsigned long long acc0 = pack2(0.f, 0.f);
        unsigned long long acc1 = acc0, acc2 = acc0, acc3 = acc0;

        for (int kh = 0; kh < 2; kh++) {
            __syncthreads();
            for (int i = tid; i < 16 * 32; i += 256) {
                int k4 = i >> 5, nn = i & 31;
                int node = tile0 + nn;
                float4 v = (node < N_NODES) ? x4[(size_t)node * 32 + kh * 16 + k4]
                                            : make_float4(0.f, 0.f, 0.f, 0.f);
                int base = (k4 * 4) * 32 + nn;
                xsf[base]      = v.x;
                xsf[base + 32] = v.y;
                xsf[base + 64] = v.z;
                xsf[base + 96] = v.w;
            }
            __syncthreads();

            const float* Wrow = &Ws[oo * 129 + kh * 64];
            const ulonglong2* vp = (const ulonglong2*)&xs2[ng * 4];
#pragma unroll 4
            for (int kk = 0; kk < 64; kk++) {
                float w = Wrow[kk];
                unsigned long long w2 = pack2(w, w);
                ulonglong2 va = vp[kk * 8];
                ulonglong2 vb = vp[kk * 8 + 1];
                FMA_F32X2(acc0, va.x, w2, acc0);
                FMA_F32X2(acc1, va.y, w2, acc1);
                FMA_F32X2(acc2, vb.x, w2, acc2);
                FMA_F32X2(acc3, vb.y, w2, acc3);
            }
        }

        int o = half * 64 + oo;
        unsigned long long accs[4] = {acc0, acc1, acc2, acc3};
#pragma unroll
        for (int j = 0; j < 4; j++) {
            float lo, hi;
            unpack2(accs[j], lo, hi);
            int n0 = tile0 + (ng * 4 + j) * 2;
            if (n0 < N_NODES)     g_xt[(size_t)n0 * 128 + o]       = __float2half_rn(lo + bias);
            if (n0 + 1 < N_NODES) g_xt[(size_t)(n0 + 1) * 128 + o] = __float2half_rn(hi + bias);
        }
    }
}

// ---------------------------------------------------------------------------
// K5: warp-per-node segmented sum over CSR (fp16 x_t, fp32 accum) + tanh.
// Unrolled x4: four independent row loads in flight per warp to beat the
// ~234cyc L2 latency (avg degree 16, serial chain before was the bottleneck).
__global__ void k_gather(float* __restrict__ out) {
    int gw   = (blockIdx.x * blockDim.x + threadIdx.x) >> 5;
    int lane = threadIdx.x & 31;
    if (gw >= N_NODES) return;

    int s = g_off[gw];
    int e = g_off[gw + 1];
    const uint2* xt2 = (const uint2*)g_xt;   // 4 halves per lane

    float4 accA = make_float4(0.f, 0.f, 0.f, 0.f);
    float4 accB = make_float4(0.f, 0.f, 0.f, 0.f);

    int i = s;
    for (; i + 3 < e; i += 4) {
        int c0 = __ldg(&g_scol[i]);
        int c1 = __ldg(&g_scol[i + 1]);
        int c2 = __ldg(&g_scol[i + 2]);
        int c3 = __ldg(&g_scol[i + 3]);
        uint2 r0 = __ldg(&xt2[(size_t)c0 * 32 + lane]);
        uint2 r1 = __ldg(&xt2[(size_t)c1 * 32 + lane]);
        uint2 r2 = __ldg(&xt2[(size_t)c2 * 32 + lane]);
        uint2 r3 = __ldg(&xt2[(size_t)c3 * 32 + lane]);
        float2 a0 = __half22float2(*(const __half2*)&r0.x);
        float2 a1 = __half22float2(*(const __half2*)&r0.y);
        float2 b0 = __half22float2(*(const __half2*)&r1.x);
        float2 b1 = __half22float2(*(const __half2*)&r1.y);
        accA.x += a0.x; accA.y += a0.y; accA.z += a1.x; accA.w += a1.y;
        accB.x += b0.x; accB.y += b0.y; accB.z += b1.x; accB.w += b1.y;
        float2 d0 = __half22float2(*(const __half2*)&r2.x);
        float2 d1 = __half22float2(*(const __half2*)&r2.y);
        float2 e0 = __half22float2(*(const __half2*)&r3.x);
        float2 e1 = __half22float2(*(const __half2*)&r3.y);
        accA.x += d0.x; accA.y += d0.y; accA.z += d1.x; accA.w += d1.y;
        accB.x += e0.x; accB.y += e0.y; accB.z += e1.x; accB.w += e1.y;
    }
    for (; i < e; i++) {
        int c = __ldg(&g_scol[i]);
        uint2 r = __ldg(&xt2[(size_t)c * 32 + lane]);
        float2 p0 = __half22float2(*(const __half2*)&r.x);
        float2 p1 = __half22float2(*(const __half2*)&r.y);
        accA.x += p0.x; accA.y += p0.y; accA.z += p1.x; accA.w += p1.y;
    }

    float4 r = make_float4(tanhf(accA.x + accB.x), tanhf(accA.y + accB.y),
                           tanhf(accA.z + accB.z), tanhf(accA.w + accB.w));
    ((float4*)out)[(size_t)gw * 32 + lane] = r;
}

// ---------------------------------------------------------------------------
extern "C" void kernel_launch(void* const* d_in, const int* in_sizes, int n_in,
                              void* d_out, int out_size) {
    const float* x  = (const float*)d_in[0];
    const void*  ei = d_in[1];
    const float* W  = (const float*)d_in[2];
    const float* b  = (const float*)d_in[3];
    float*       out = (float*)d_out;

    k_detect<<<1, 32>>>(ei);
    k_zero<<<(N_NODES + 255) / 256, 256>>>();
    k_count<<<(N_EDGES + 255) / 256, 256>>>(ei);

    // Launch slot 4 = profiled slot. Linear is CSR-independent, so hoist it
    // here to get it under the profiler this round.
    dim3 lgrid((N_NODES + NODES_PER_BLOCK - 1) / NODES_PER_BLOCK, 2);
    k_linear<<<lgrid, 256>>>(x, W, b);

    k_scan1<<<SCAN_BLOCKS, 256>>>();
    k_scan2<<<1, 256>>>();
    k_scan3<<<SCAN_BLOCKS, 256>>>();
    k_scatter<<<(N_EDGES + 255) / 256, 256>>>(ei);

    k_gather<<<(N_NODES * 32 + 255) / 256, 256>>>(out);
}

// round 6
// speedup vs baseline: 1.9921x; 1.2150x over previous
#include <cuda_runtime.h>
#include <cuda_fp16.h>

#define N_NODES 50000
#define N_EDGES 800000
#define CIN 128
#define COUT 128

#define SCAN_BLOCKS ((N_NODES + 255) / 256)   // 196

// Scratch (allocation-free: __device__ globals)
__device__ int    g_is64;
__device__ int    g_deg[N_NODES];
__device__ int    g_off[N_NODES + 1];
__device__ int    g_cur[N_NODES];
__device__ int    g_part[SCAN_BLOCKS];
__device__ int    g_scol[N_EDGES];
__device__ __half g_Wt[CIN * COUT];               // W transposed [k][oc], fp16
__device__ __half g_xt[(size_t)N_NODES * COUT];   // fp16 transformed features

// Packed fp32x2 FMA (Blackwell FFMA2 — only reachable via PTX fma.rn.f32x2)
#define FMA_F32X2(d, a, b, c) \
    asm("fma.rn.f32x2 %0, %1, %2, %3;" : "=l"(d) : "l"(a), "l"(b), "l"(c))

__device__ __forceinline__ unsigned long long pack2(float lo, float hi) {
    unsigned long long r;
    asm("mov.b64 %0, {%1, %2};" : "=l"(r) : "f"(lo), "f"(hi));
    return r;
}
__device__ __forceinline__ void unpack2(unsigned long long v, float& lo, float& hi) {
    asm("mov.b64 {%0, %1}, %2;" : "=f"(lo), "=f"(hi) : "l"(v));
}

// ---------------------------------------------------------------------------
// KD: detect edge_index dtype (int64 layout -> every 8B word in [0, N_NODES)).
__global__ void k_detect(const void* ei_raw) {
    if (threadIdx.x == 0 && blockIdx.x == 0) {
        const long long* p = (const long long*)ei_raw;
        int ok = 1;
        for (int i = 0; i < 64; i++) {
            long long v = p[i];
            if (v < 0 || v >= N_NODES) { ok = 0; break; }
        }
        g_is64 = ok;
    }
}

__device__ __forceinline__ int load_edge(const void* ei_raw, long long idx) {
    if (g_is64) return (int)((const long long*)ei_raw)[idx];
    return ((const int*)ei_raw)[idx];
}

// ---------------------------------------------------------------------------
// KW: one-shot W transpose + fp16 convert: g_Wt[k][oc] = (half)W[oc][k].
// Grid 16 blocks of 1024 (32x32 tiles, padded smem -> conflict-free).
__global__ void k_wt(const float* __restrict__ W) {
    __shared__ float t[32][33];
    int bx = blockIdx.x & 3, by = blockIdx.x >> 2;
    int tx = threadIdx.x & 31, ty = threadIdx.x >> 5;
    t[ty][tx] = W[(by * 32 + ty) * CIN + bx * 32 + tx];
    __syncthreads();
    g_Wt[(bx * 32 + ty) * COUT + by * 32 + tx] = __float2half_rn(t[tx][ty]);
}

// ---------------------------------------------------------------------------
__global__ void k_zero() {
    int i = blockIdx.x * blockDim.x + threadIdx.x;
    if (i < N_NODES) g_deg[i] = 0;
}

__global__ void k_count(const void* __restrict__ ei) {
    int e = blockIdx.x * blockDim.x + threadIdx.x;
    if (e < N_EDGES) {
        int r = load_edge(ei, e);
        if (r >= 0 && r < N_NODES) atomicAdd(&g_deg[r], 1);
    }
}

// ---------------------------------------------------------------------------
// Multi-block exclusive scan of g_deg -> g_off / g_cur.
__global__ void k_scan1() {
    __shared__ int warpsum[8];
    int i = blockIdx.x * 256 + threadIdx.x;
    int v = (i < N_NODES) ? g_deg[i] : 0;
#pragma unroll
    for (int d = 16; d > 0; d >>= 1) v += __shfl_down_sync(0xffffffffu, v, d);
    if ((threadIdx.x & 31) == 0) warpsum[threadIdx.x >> 5] = v;
    __syncthreads();
    if (threadIdx.x < 8) {
        int s = warpsum[threadIdx.x];
#pragma unroll
        for (int d = 4; d > 0; d >>= 1) s += __shfl_down_sync(0xffu, s, d);
        if (threadIdx.x == 0) g_part[blockIdx.x] = s;
    }
}

__global__ void k_scan2() {
    __shared__ int sp[256];
    int tid = threadIdx.x;
    int v = (tid < SCAN_BLOCKS) ? g_part[tid] : 0;
    sp[tid] = v;
    __syncthreads();
#pragma unroll
    for (int d = 1; d < 256; d <<= 1) {
        int u = (tid >= d) ? sp[tid - d] : 0;
        __syncthreads();
        sp[tid] += u;
        __syncthreads();
    }
    if (tid < SCAN_BLOCKS) g_part[tid] = (tid == 0) ? 0 : sp[tid - 1];
    if (tid == 255) g_off[N_NODES] = sp[255];
}

__global__ void k_scan3() {
    __shared__ int sv[256];
    int tid = threadIdx.x;
    int i = blockIdx.x * 256 + tid;
    int v = (i < N_NODES) ? g_deg[i] : 0;
    sv[tid] = v;
    __syncthreads();
#pragma unroll
    for (int d = 1; d < 256; d <<= 1) {
        int u = (tid >= d) ? sv[tid - d] : 0;
        __syncthreads();
        sv[tid] += u;
        __syncthreads();
    }
    if (i < N_NODES) {
        int excl = g_part[blockIdx.x] + sv[tid] - v;
        g_off[i] = excl;
        g_cur[i] = excl;
    }
}

// ---------------------------------------------------------------------------
__global__ void k_scatter(const void* __restrict__ ei) {
    int e = blockIdx.x * blockDim.x + threadIdx.x;
    if (e < N_EDGES) {
        int r = load_edge(ei, e);
        int c = load_edge(ei, (long long)e + N_EDGES);
        if (r >= 0 && r < N_NODES && c >= 0 && c < N_NODES) {
            int p = atomicAdd(&g_cur[r], 1);
            g_scol[p] = c;
        }
    }
}

// ---------------------------------------------------------------------------
// K4: x_t = x @ W^T + b. Register-blocked outer product, FFMA2.
// Block = 128 thr = 4 warps. lane -> 4 out-channels (oc = lane*4+j),
// warp -> 4 node pairs (8 nodes). Per thread: 16 f32x2 accumulators.
// Smem/k per thread: 8B W (fp16 x4, contiguous) + 32B x (warp broadcast)
// = 1.25 B/MAC -> FMA-bound.
#define NODES_PER_BLOCK 64
__global__ void __launch_bounds__(128) k_linear(const float* __restrict__ x,
                                                const float* __restrict__ b) {
    __shared__ __align__(16) __half          Wh[CIN * COUT];   // [k][oc] 32KB
    __shared__ __align__(16) unsigned long long xs2[CIN * 16]; // [k][pair] 16KB

    int tid  = threadIdx.x;
    int lane = tid & 31;
    int warp = tid >> 5;

    // Wh <- g_Wt, coalesced 16B copies (both [k][oc], no transpose needed).
    {
        const uint4* src = (const uint4*)g_Wt;
        uint4*       dst = (uint4*)Wh;
        for (int i = tid; i < CIN * COUT * 2 / 16; i += 128) dst[i] = src[i];
    }
    float4 bias = ((const float4*)b)[lane];

    const float4* x4  = (const float4*)x;
    float*        xsf = (float*)xs2;
    int nb0 = blockIdx.x * NODES_PER_BLOCK;

    for (int t = 0; t < NODES_PER_BLOCK / 32; t++) {
        int tile0 = nb0 + t * 32;
        __syncthreads();  // xs2 reuse (covers Wh load on first pass)
        // Transpose-load 32 nodes x 128 k into xs2[k][pair].
        for (int i = tid; i < 1024; i += 128) {
            int nn = i & 31, k4 = i >> 5;    // k4: 0..31 float4-chunks of k
            int node = tile0 + nn;
            float4 v = (node < N_NODES) ? x4[(size_t)node * 32 + k4]
                                        : make_float4(0.f, 0.f, 0.f, 0.f);
            int base = (k4 * 4) * 32 + nn;
            xsf[base]      = v.x;
            xsf[base + 32] = v.y;
            xsf[base + 64] = v.z;
            xsf[base + 96] = v.w;
        }
        __syncthreads();

        unsigned long long acc[4][4];        // [oc_j][pair_p]
#pragma unroll
        for (int j = 0; j < 4; j++)
#pragma unroll
            for (int p = 0; p < 4; p++) acc[j][p] = 0ull;

        const uint2*      wp = (const uint2*)&Wh[lane * 4];          // +k*128 halves
        const ulonglong2* xp = (const ulonglong2*)&xs2[warp * 4];    // +k*16 ull

#pragma unroll 8
        for (int k = 0; k < CIN; k++) {
            uint2 wraw = wp[k * 32];         // 4 fp16 weights (8B stride-128h rows)
            float2 w01 = __half22float2(*(const __half2*)&wraw.x);
            float2 w23 = __half22float2(*(const __half2*)&wraw.y);
            unsigned long long w0 = pack2(w01.x, w01.x);
            unsigned long long w1 = pack2(w01.y, w01.y);
            unsigned long long w2 = pack2(w23.x, w23.x);
            unsigned long long w3 = pack2(w23.y, w23.y);
            ulonglong2 va = xp[k * 8];       // pairs warp*4+0,1 (broadcast)
            ulonglong2 vb = xp[k * 8 + 1];   // pairs warp*4+2,3
            FMA_F32X2(acc[0][0], va.x, w0, acc[0][0]);
            FMA_F32X2(acc[1][0], va.x, w1, acc[1][0]);
            FMA_F32X2(acc[2][0], va.x, w2, acc[2][0]);
            FMA_F32X2(acc[3][0], va.x, w3, acc[3][0]);
            FMA_F32X2(acc[0][1], va.y, w0, acc[0][1]);
            FMA_F32X2(acc[1][1], va.y, w1, acc[1][1]);
            FMA_F32X2(acc[2][1], va.y, w2, acc[2][1]);
            FMA_F32X2(acc[3][1], va.y, w3, acc[3][1]);
            FMA_F32X2(acc[0][2], vb.x, w0, acc[0][2]);
            FMA_F32X2(acc[1][2], vb.x, w1, acc[1][2]);
            FMA_F32X2(acc[2][2], vb.x, w2, acc[2][2]);
            FMA_F32X2(acc[3][2], vb.x, w3, acc[3][2]);
            FMA_F32X2(acc[0][3], vb.y, w0, acc[0][3]);
            FMA_F32X2(acc[1][3], vb.y, w1, acc[1][3]);
            FMA_F32X2(acc[2][3], vb.y, w2, acc[2][3]);
            FMA_F32X2(acc[3][3], vb.y, w3, acc[3][3]);
        }

        // Store: per pair p -> nodes n0, n0+1; 4 oc as 2 half2 (8B coalesced).
#pragma unroll
        for (int p = 0; p < 4; p++) {
            int n0 = tile0 + (warp * 4 + p) * 2;
            float lo0, hi0, lo1, hi1, lo2, hi2, lo3, hi3;
            unpack2(acc[0][p], lo0, hi0);
            unpack2(acc[1][p], lo1, hi1);
            unpack2(acc[2][p], lo2, hi2);
            unpack2(acc[3][p], lo3, hi3);
            if (n0 < N_NODES) {
                __half2 h0 = __floats2half2_rn(lo0 + bias.x, lo1 + bias.y);
                __half2 h1 = __floats2half2_rn(lo2 + bias.z, lo3 + bias.w);
                uint2 st = { *(unsigned*)&h0, *(unsigned*)&h1 };
                *(uint2*)&g_xt[(size_t)n0 * COUT + lane * 4] = st;
            }
            if (n0 + 1 < N_NODES) {
                __half2 h0 = __floats2half2_rn(hi0 + bias.x, hi1 + bias.y);
                __half2 h1 = __floats2half2_rn(hi2 + bias.z, hi3 + bias.w);
                uint2 st = { *(unsigned*)&h0, *(unsigned*)&h1 };
                *(uint2*)&g_xt[(size_t)(n0 + 1) * COUT + lane * 4] = st;
            }
        }
    }
}

// ---------------------------------------------------------------------------
// K5: warp-per-node segmented sum over CSR (fp16 x_t, fp32 accum) + tanh.
__global__ void k_gather(float* __restrict__ out) {
    int gw   = (blockIdx.x * blockDim.x + threadIdx.x) >> 5;
    int lane = threadIdx.x & 31;
    if (gw >= N_NODES) return;

    int s = g_off[gw];
    int e = g_off[gw + 1];
    const uint2* xt2 = (const uint2*)g_xt;

    float4 accA = make_float4(0.f, 0.f, 0.f, 0.f);
    float4 accB = make_float4(0.f, 0.f, 0.f, 0.f);

    int i = s;
    for (; i + 3 < e; i += 4) {
        int c0 = __ldg(&g_scol[i]);
        int c1 = __ldg(&g_scol[i + 1]);
        int c2 = __ldg(&g_scol[i + 2]);
        int c3 = __ldg(&g_scol[i + 3]);
        uint2 r0 = __ldg(&xt2[(size_t)c0 * 32 + lane]);
        uint2 r1 = __ldg(&xt2[(size_t)c1 * 32 + lane]);
        uint2 r2 = __ldg(&xt2[(size_t)c2 * 32 + lane]);
        uint2 r3 = __ldg(&xt2[(size_t)c3 * 32 + lane]);
        float2 a0 = __half22float2(*(const __half2*)&r0.x);
        float2 a1 = __half22float2(*(const __half2*)&r0.y);
        float2 b0 = __half22float2(*(const __half2*)&r1.x);
        float2 b1 = __half22float2(*(const __half2*)&r1.y);
        accA.x += a0.x; accA.y += a0.y; accA.z += a1.x; accA.w += a1.y;
        accB.x += b0.x; accB.y += b0.y; accB.z += b1.x; accB.w += b1.y;
        float2 d0 = __half22float2(*(const __half2*)&r2.x);
        float2 d1 = __half22float2(*(const __half2*)&r2.y);
        float2 e0 = __half22float2(*(const __half2*)&r3.x);
        float2 e1 = __half22float2(*(const __half2*)&r3.y);
        accA.x += d0.x; accA.y += d0.y; accA.z += d1.x; accA.w += d1.y;
        accB.x += e0.x; accB.y += e0.y; accB.z += e1.x; accB.w += e1.y;
    }
    for (; i < e; i++) {
        int c = __ldg(&g_scol[i]);
        uint2 r = __ldg(&xt2[(size_t)c * 32 + lane]);
        float2 p0 = __half22float2(*(const __half2*)&r.x);
        float2 p1 = __half22float2(*(const __half2*)&r.y);
        accA.x += p0.x; accA.y += p0.y; accA.z += p1.x; accA.w += p1.y;
    }

    float4 r = make_float4(tanhf(accA.x + accB.x), tanhf(accA.y + accB.y),
                           tanhf(accA.z + accB.z), tanhf(accA.w + accB.w));
    ((float4*)out)[(size_t)gw * 32 + lane] = r;
}

// ---------------------------------------------------------------------------
extern "C" void kernel_launch(void* const* d_in, const int* in_sizes, int n_in,
                              void* d_out, int out_size) {
    const float* x  = (const float*)d_in[0];
    const void*  ei = d_in[1];
    const float* W  = (const float*)d_in[2];
    const float* b  = (const float*)d_in[3];
    float*       out = (float*)d_out;

    k_detect<<<1, 32>>>(ei);                      // slot 1
    k_wt<<<16, 1024>>>(W);                        // slot 2
    k_zero<<<(N_NODES + 255) / 256, 256>>>();     // slot 3

    // slot 4 = profiled slot: keep k_linear here to verify the LDS fix.
    k_linear<<<(N_NODES + NODES_PER_BLOCK - 1) / NODES_PER_BLOCK, 128>>>(x, b);

    k_count<<<(N_EDGES + 255) / 256, 256>>>(ei);
    k_scan1<<<SCAN_BLOCKS, 256>>>();
    k_scan2<<<1, 256>>>();
    k_scan3<<<SCAN_BLOCKS, 256>>>();
    k_scatter<<<(N_EDGES + 255) / 256, 256>>>(ei);

    k_gather<<<(N_NODES * 32 + 255) / 256, 256>>>(out);
}

// round 7
// speedup vs baseline: 2.6510x; 1.3308x over previous
#include <cuda_runtime.h>
#include <cuda_fp16.h>

#define N_NODES 50000
#define N_EDGES 800000
#define CIN 128
#define COUT 128

#define SCAN_BLOCKS ((N_NODES + 255) / 256)   // 196

// Scratch (allocation-free: __device__ globals)
__device__ int    g_is64;
__device__ int    g_deg[N_NODES];
__device__ int    g_off[N_NODES + 1];
__device__ int    g_cur[N_NODES];
__device__ int    g_part[SCAN_BLOCKS];
__device__ int    g_scol[N_EDGES];
__device__ __half g_xt[(size_t)N_NODES * COUT];   // fp16 transformed features

// ---------------------------------------------------------------------------
__device__ __forceinline__ void ldsm_x4(unsigned* r, unsigned addr) {
    asm volatile("ldmatrix.sync.aligned.m8n8.x4.shared.b16 {%0,%1,%2,%3}, [%4];"
                 : "=r"(r[0]), "=r"(r[1]), "=r"(r[2]), "=r"(r[3]) : "r"(addr));
}
__device__ __forceinline__ void mma16816(float* c, const unsigned* a, const unsigned* b) {
    asm volatile(
        "mma.sync.aligned.m16n8k16.row.col.f32.f16.f16.f32 "
        "{%0,%1,%2,%3}, {%4,%5,%6,%7}, {%8,%9}, {%0,%1,%2,%3};"
        : "+f"(c[0]), "+f"(c[1]), "+f"(c[2]), "+f"(c[3])
        : "r"(a[0]), "r"(a[1]), "r"(a[2]), "r"(a[3]), "r"(b[0]), "r"(b[1]));
}

// ---------------------------------------------------------------------------
// KD: detect edge_index dtype (int64 layout -> every 8B word in [0, N_NODES)).
__global__ void k_detect(const void* ei_raw) {
    if (threadIdx.x == 0 && blockIdx.x == 0) {
        const long long* p = (const long long*)ei_raw;
        int ok = 1;
        for (int i = 0; i < 64; i++) {
            long long v = p[i];
            if (v < 0 || v >= N_NODES) { ok = 0; break; }
        }
        g_is64 = ok;
    }
}

__device__ __forceinline__ int load_edge(const void* ei_raw, long long idx) {
    if (g_is64) return (int)((const long long*)ei_raw)[idx];
    return ((const int*)ei_raw)[idx];
}

// ---------------------------------------------------------------------------
__global__ void k_zero() {
    int i = blockIdx.x * blockDim.x + threadIdx.x;
    if (i < N_NODES) g_deg[i] = 0;
}

__global__ void k_count(const void* __restrict__ ei) {
    int e = blockIdx.x * blockDim.x + threadIdx.x;
    if (e < N_EDGES) {
        int r = load_edge(ei, e);
        if (r >= 0 && r < N_NODES) atomicAdd(&g_deg[r], 1);
    }
}

// ---------------------------------------------------------------------------
// K4: x_t = x @ W^T + b via HMMA m16n8k16, fp16 in / fp32 accum / fp16 out.
// Block = 128 thr (4 warps) computes 64 nodes x 64 oc (half = blockIdx.y).
// A smem [m][k] fp16 stride 136 (ldmatrix conflict-free: 272B rows = 4-bank
// shift/row). B = W[oc][k] (k-contiguous) = col-major operand, same layout.
#define LSTRIDE 136
__global__ void __launch_bounds__(128) k_linear(const float* __restrict__ x,
                                                const float* __restrict__ W,
                                                const float* __restrict__ b) {
    __shared__ __align__(16) __half As[64 * LSTRIDE];
    __shared__ __align__(16) __half Bs[64 * LSTRIDE];

    int tid = threadIdx.x, lane = tid & 31, warp = tid >> 5;
    int half = blockIdx.y;
    int m0 = blockIdx.x * 64;

    // A tile: x[m0..m0+63][0..127] fp32 -> fp16. Lane covers 512B/node: coalesced.
    const float4* x4 = (const float4*)x;
    for (int idx = tid; idx < 64 * 32; idx += 128) {
        int nn = idx >> 5, k4 = idx & 31;
        int node = m0 + nn;
        float4 v = (node < N_NODES) ? x4[(size_t)node * 32 + k4]
                                    : make_float4(0.f, 0.f, 0.f, 0.f);
        __half2 h0 = __floats2half2_rn(v.x, v.y);
        __half2 h1 = __floats2half2_rn(v.z, v.w);
        uint2 st = { *(unsigned*)&h0, *(unsigned*)&h1 };
        *(uint2*)&As[nn * LSTRIDE + k4 * 4] = st;
    }
    // B tile: W[half*64+n][0..127] fp32 -> fp16 (no transpose: already [n][k]).
    const float4* w4 = (const float4*)W;
    for (int idx = tid; idx < 64 * 32; idx += 128) {
        int nn = idx >> 5, k4 = idx & 31;
        float4 v = w4[(size_t)(half * 64 + nn) * 32 + k4];
        __half2 h0 = __floats2half2_rn(v.x, v.y);
        __half2 h1 = __floats2half2_rn(v.z, v.w);
        uint2 st = { *(unsigned*)&h0, *(unsigned*)&h1 };
        *(uint2*)&Bs[nn * LSTRIDE + k4 * 4] = st;
    }
    __syncthreads();

    float acc[8][4];
#pragma unroll
    for (int i = 0; i < 8; i++)
#pragma unroll
        for (int j = 0; j < 4; j++) acc[i][j] = 0.f;

    unsigned a_base = (unsigned)__cvta_generic_to_shared(As);
    unsigned b_base = (unsigned)__cvta_generic_to_shared(Bs);
    int m_warp = warp * 16;

    // A x4 lane addr: row = m_warp + lane%16, col = kk*16 + (lane/16)*8
    unsigned a_off = a_base + ((m_warp + (lane & 15)) * LSTRIDE + (lane >> 4) * 8) * 2;
    // B x4 lane addr (pair of n-tiles ntp): rows ntp*16 + (lane/16)*8 + lane%8,
    // col = kk*16 + ((lane/8)%2)*8 -> frags {nt,k0-7},{nt,k8-15},{nt+1,...}
    unsigned b_off = b_base + (((lane >> 4) << 3) + (lane & 7)) * LSTRIDE * 2
                            + (((lane >> 3) & 1) * 8) * 2;

#pragma unroll
    for (int kk = 0; kk < 8; kk++) {
        unsigned a[4];
        ldsm_x4(a, a_off + kk * 32);         // 16 halves = 32B per k-step
#pragma unroll
        for (int ntp = 0; ntp < 4; ntp++) {
            unsigned bf[4];
            ldsm_x4(bf, b_off + (ntp * 16 * LSTRIDE) * 2 + kk * 32);
            mma16816(acc[ntp * 2],     a, bf);
            mma16816(acc[ntp * 2 + 1], a, bf + 2);
        }
    }

    // Store C: lane holds rows (lane/4, lane/4+8), cols (lane%4)*2 per n-tile.
    int row0 = m_warp + (lane >> 2);
#pragma unroll
    for (int nt = 0; nt < 8; nt++) {
        int col = half * 64 + nt * 8 + (lane & 3) * 2;
        float2 bv = *(const float2*)&b[col];
        int na = m0 + row0;
        if (na < N_NODES) {
            __half2 h = __floats2half2_rn(acc[nt][0] + bv.x, acc[nt][1] + bv.y);
            *(__half2*)&g_xt[(size_t)na * COUT + col] = h;
        }
        int nb = na + 8;
        if (nb < N_NODES) {
            __half2 h = __floats2half2_rn(acc[nt][2] + bv.x, acc[nt][3] + bv.y);
            *(__half2*)&g_xt[(size_t)nb * COUT + col] = h;
        }
    }
}

// ---------------------------------------------------------------------------
// Multi-block exclusive scan of g_deg -> g_off / g_cur.
__global__ void k_scan1() {
    __shared__ int warpsum[8];
    int i = blockIdx.x * 256 + threadIdx.x;
    int v = (i < N_NODES) ? g_deg[i] : 0;
#pragma unroll
    for (int d = 16; d > 0; d >>= 1) v += __shfl_down_sync(0xffffffffu, v, d);
    if ((threadIdx.x & 31) == 0) warpsum[threadIdx.x >> 5] = v;
    __syncthreads();
    if (threadIdx.x < 8) {
        int s = warpsum[threadIdx.x];
#pragma unroll
        for (int d = 4; d > 0; d >>= 1) s += __shfl_down_sync(0xffu, s, d);
        if (threadIdx.x == 0) g_part[blockIdx.x] = s;
    }
}

__global__ void k_scan2() {
    __shared__ int sp[256];
    int tid = threadIdx.x;
    int v = (tid < SCAN_BLOCKS) ? g_part[tid] : 0;
    sp[tid] = v;
    __syncthreads();
#pragma unroll
    for (int d = 1; d < 256; d <<= 1) {
        int u = (tid >= d) ? sp[tid - d] : 0;
        __syncthreads();
        sp[tid] += u;
        __syncthreads();
    }
    if (tid < SCAN_BLOCKS) g_part[tid] = (tid == 0) ? 0 : sp[tid - 1];
    if (tid == 255) g_off[N_NODES] = sp[255];
}

__global__ void k_scan3() {
    __shared__ int sv[256];
    int tid = threadIdx.x;
    int i = blockIdx.x * 256 + tid;
    int v = (i < N_NODES) ? g_deg[i] : 0;
    sv[tid] = v;
    __syncthreads();
#pragma unroll
    for (int d = 1; d < 256; d <<= 1) {
        int u = (tid >= d) ? sv[tid - d] : 0;
        __syncthreads();
        sv[tid] += u;
        __syncthreads();
    }
    if (i < N_NODES) {
        int excl = g_part[blockIdx.x] + sv[tid] - v;
        g_off[i] = excl;
        g_cur[i] = excl;
    }
}

// ---------------------------------------------------------------------------
__global__ void k_scatter(const void* __restrict__ ei) {
    int e = blockIdx.x * blockDim.x + threadIdx.x;
    if (e < N_EDGES) {
        int r = load_edge(ei, e);
        int c = load_edge(ei, (long long)e + N_EDGES);
        if (r >= 0 && r < N_NODES && c >= 0 && c < N_NODES) {
            int p = atomicAdd(&g_cur[r], 1);
            g_scol[p] = c;
        }
    }
}

// ---------------------------------------------------------------------------
// K5: warp-per-node segmented sum over CSR (fp16 x_t, fp32 accum) + tanh.
__global__ void k_gather(float* __restrict__ out) {
    int gw   = (blockIdx.x * blockDim.x + threadIdx.x) >> 5;
    int lane = threadIdx.x & 31;
    if (gw >= N_NODES) return;

    int s = g_off[gw];
    int e = g_off[gw + 1];
    const uint2* xt2 = (const uint2*)g_xt;

    float4 accA = make_float4(0.f, 0.f, 0.f, 0.f);
    float4 accB = make_float4(0.f, 0.f, 0.f, 0.f);

    int i = s;
    for (; i + 3 < e; i += 4) {
        int c0 = __ldg(&g_scol[i]);
        int c1 = __ldg(&g_scol[i + 1]);
        int c2 = __ldg(&g_scol[i + 2]);
        int c3 = __ldg(&g_scol[i + 3]);
        uint2 r0 = __ldg(&xt2[(size_t)c0 * 32 + lane]);
        uint2 r1 = __ldg(&xt2[(size_t)c1 * 32 + lane]);
        uint2 r2 = __ldg(&xt2[(size_t)c2 * 32 + lane]);
        uint2 r3 = __ldg(&xt2[(size_t)c3 * 32 + lane]);
        float2 a0 = __half22float2(*(const __half2*)&r0.x);
        float2 a1 = __half22float2(*(const __half2*)&r0.y);
        float2 b0 = __half22float2(*(const __half2*)&r1.x);
        float2 b1 = __half22float2(*(const __half2*)&r1.y);
        accA.x += a0.x; accA.y += a0.y; accA.z += a1.x; accA.w += a1.y;
        accB.x += b0.x; accB.y += b0.y; accB.z += b1.x; accB.w += b1.y;
        float2 d0 = __half22float2(*(const __half2*)&r2.x);
        float2 d1 = __half22float2(*(const __half2*)&r2.y);
        float2 e0 = __half22float2(*(const __half2*)&r3.x);
        float2 e1 = __half22float2(*(const __half2*)&r3.y);
        accA.x += d0.x; accA.y += d0.y; accA.z += d1.x; accA.w += d1.y;
        accB.x += e0.x; accB.y += e0.y; accB.z += e1.x; accB.w += e1.y;
    }
    for (; i < e; i++) {
        int c = __ldg(&g_scol[i]);
        uint2 r = __ldg(&xt2[(size_t)c * 32 + lane]);
        float2 p0 = __half22float2(*(const __half2*)&r.x);
        float2 p1 = __half22float2(*(const __half2*)&r.y);
        accA.x += p0.x; accA.y += p0.y; accA.z += p1.x; accA.w += p1.y;
    }

    float4 r = make_float4(tanhf(accA.x + accB.x), tanhf(accA.y + accB.y),
                           tanhf(accA.z + accB.z), tanhf(accA.w + accB.w));
    ((float4*)out)[(size_t)gw * 32 + lane] = r;
}

// ---------------------------------------------------------------------------
extern "C" void kernel_launch(void* const* d_in, const int* in_sizes, int n_in,
                              void* d_out, int out_size) {
    const float* x  = (const float*)d_in[0];
    const void*  ei = d_in[1];
    const float* W  = (const float*)d_in[2];
    const float* b  = (const float*)d_in[3];
    float*       out = (float*)d_out;

    k_detect<<<1, 32>>>(ei);                      // slot 1
    k_zero<<<(N_NODES + 255) / 256, 256>>>();     // slot 2
    k_count<<<(N_EDGES + 255) / 256, 256>>>(ei);  // slot 3

    // slot 4 = profiled slot: verify the HMMA linear this round.
    dim3 lgrid((N_NODES + 63) / 64, 2);
    k_linear<<<lgrid, 128>>>(x, W, b);

    k_scan1<<<SCAN_BLOCKS, 256>>>();
    k_scan2<<<1, 256>>>();
    k_scan3<<<SCAN_BLOCKS, 256>>>();
    k_scatter<<<(N_EDGES + 255) / 256, 256>>>(ei);

    k_gather<<<(N_NODES * 32 + 255) / 256, 256>>>(out);
}

// round 8
// speedup vs baseline: 2.9799x; 1.1241x over previous
#include <cuda_runtime.h>
#include <cuda_fp16.h>

#define N_NODES 50000
#define N_EDGES 800000
#define CIN 128
#define COUT 128

#define SCAN_BLOCKS ((N_NODES + 255) / 256)   // 196

// Scratch (allocation-free: __device__ globals)
__device__ int    g_is64;
__device__ int    g_deg[N_NODES];
__device__ int    g_off[N_NODES + 1];
__device__ int    g_cur[N_NODES];
__device__ int    g_part[SCAN_BLOCKS];
__device__ int    g_scol[N_EDGES];
__device__ __half g_xt[(size_t)N_NODES * COUT];   // fp16 transformed features

// ---------------------------------------------------------------------------
__device__ __forceinline__ void ldsm_x4(unsigned* r, unsigned addr) {
    asm volatile("ldmatrix.sync.aligned.m8n8.x4.shared.b16 {%0,%1,%2,%3}, [%4];"
                 : "=r"(r[0]), "=r"(r[1]), "=r"(r[2]), "=r"(r[3]) : "r"(addr));
}
__device__ __forceinline__ void mma16816(float* c, const unsigned* a, const unsigned* b) {
    asm volatile(
        "mma.sync.aligned.m16n8k16.row.col.f32.f16.f16.f32 "
        "{%0,%1,%2,%3}, {%4,%5,%6,%7}, {%8,%9}, {%0,%1,%2,%3};"
        : "+f"(c[0]), "+f"(c[1]), "+f"(c[2]), "+f"(c[3])
        : "r"(a[0]), "r"(a[1]), "r"(a[2]), "r"(a[3]), "r"(b[0]), "r"(b[1]));
}

// ---------------------------------------------------------------------------
// KD: detect edge_index dtype — PARALLEL (was a 64-iter serial latency chain).
__global__ void k_detect(const void* ei_raw) {
    const long long* p = (const long long*)ei_raw;
    int lane = threadIdx.x;           // 32 threads, 2 elems each
    long long v0 = p[lane];
    long long v1 = p[lane + 32];
    int bad = (v0 < 0 || v0 >= N_NODES || v1 < 0 || v1 >= N_NODES);
    unsigned m = __ballot_sync(0xffffffffu, bad);
    if (lane == 0) g_is64 = (m == 0);
}

__device__ __forceinline__ int load_edge(const void* ei_raw, long long idx) {
    if (g_is64) return (int)((const long long*)ei_raw)[idx];
    return ((const int*)ei_raw)[idx];
}

// ---------------------------------------------------------------------------
__global__ void k_zero() {
    int i = blockIdx.x * blockDim.x + threadIdx.x;
    if (i < N_NODES) g_deg[i] = 0;
}

__global__ void k_count(const void* __restrict__ ei) {
    int e = blockIdx.x * blockDim.x + threadIdx.x;
    if (e < N_EDGES) {
        int r = load_edge(ei, e);
        if (r >= 0 && r < N_NODES) atomicAdd(&g_deg[r], 1);
    }
}

// ---------------------------------------------------------------------------
// K4: x_t = x @ W^T + b via HMMA m16n8k16 (unchanged from R7).
#define LSTRIDE 136
__global__ void __launch_bounds__(128) k_linear(const float* __restrict__ x,
                                                const float* __restrict__ W,
                                                const float* __restrict__ b) {
    __shared__ __align__(16) __half As[64 * LSTRIDE];
    __shared__ __align__(16) __half Bs[64 * LSTRIDE];

    int tid = threadIdx.x, lane = tid & 31, warp = tid >> 5;
    int half = blockIdx.y;
    int m0 = blockIdx.x * 64;

    const float4* x4 = (const float4*)x;
    for (int idx = tid; idx < 64 * 32; idx += 128) {
        int nn = idx >> 5, k4 = idx & 31;
        int node = m0 + nn;
        float4 v = (node < N_NODES) ? x4[(size_t)node * 32 + k4]
                                    : make_float4(0.f, 0.f, 0.f, 0.f);
        __half2 h0 = __floats2half2_rn(v.x, v.y);
        __half2 h1 = __floats2half2_rn(v.z, v.w);
        uint2 st = { *(unsigned*)&h0, *(unsigned*)&h1 };
        *(uint2*)&As[nn * LSTRIDE + k4 * 4] = st;
    }
    const float4* w4 = (const float4*)W;
    for (int idx = tid; idx < 64 * 32; idx += 128) {
        int nn = idx >> 5, k4 = idx & 31;
        float4 v = w4[(size_t)(half * 64 + nn) * 32 + k4];
        __half2 h0 = __floats2half2_rn(v.x, v.y);
        __half2 h1 = __floats2half2_rn(v.z, v.w);
        uint2 st = { *(unsigned*)&h0, *(unsigned*)&h1 };
        *(uint2*)&Bs[nn * LSTRIDE + k4 * 4] = st;
    }
    __syncthreads();

    float acc[8][4];
#pragma unroll
    for (int i = 0; i < 8; i++)
#pragma unroll
        for (int j = 0; j < 4; j++) acc[i][j] = 0.f;

    unsigned a_base = (unsigned)__cvta_generic_to_shared(As);
    unsigned b_base = (unsigned)__cvta_generic_to_shared(Bs);
    int m_warp = warp * 16;

    unsigned a_off = a_base + ((m_warp + (lane & 15)) * LSTRIDE + (lane >> 4) * 8) * 2;
    unsigned b_off = b_base + (((lane >> 4) << 3) + (lane & 7)) * LSTRIDE * 2
                            + (((lane >> 3) & 1) * 8) * 2;

#pragma unroll
    for (int kk = 0; kk < 8; kk++) {
        unsigned a[4];
        ldsm_x4(a, a_off + kk * 32);
#pragma unroll
        for (int ntp = 0; ntp < 4; ntp++) {
            unsigned bf[4];
            ldsm_x4(bf, b_off + (ntp * 16 * LSTRIDE) * 2 + kk * 32);
            mma16816(acc[ntp * 2],     a, bf);
            mma16816(acc[ntp * 2 + 1], a, bf + 2);
        }
    }

    int row0 = m_warp + (lane >> 2);
#pragma unroll
    for (int nt = 0; nt < 8; nt++) {
        int col = half * 64 + nt * 8 + (lane & 3) * 2;
        float2 bv = *(const float2*)&b[col];
        int na = m0 + row0;
        if (na < N_NODES) {
            __half2 h = __floats2half2_rn(acc[nt][0] + bv.x, acc[nt][1] + bv.y);
            *(__half2*)&g_xt[(size_t)na * COUT + col] = h;
        }
        int nb = na + 8;
        if (nb < N_NODES) {
            __half2 h = __floats2half2_rn(acc[nt][2] + bv.x, acc[nt][3] + bv.y);
            *(__half2*)&g_xt[(size_t)nb * COUT + col] = h;
        }
    }
}

// ---------------------------------------------------------------------------
// Multi-block exclusive scan of g_deg -> g_off / g_cur.
__global__ void k_scan1() {
    __shared__ int warpsum[8];
    int i = blockIdx.x * 256 + threadIdx.x;
    int v = (i < N_NODES) ? g_deg[i] : 0;
#pragma unroll
    for (int d = 16; d > 0; d >>= 1) v += __shfl_down_sync(0xffffffffu, v, d);
    if ((threadIdx.x & 31) == 0) warpsum[threadIdx.x >> 5] = v;
    __syncthreads();
    if (threadIdx.x < 8) {
        int s = warpsum[threadIdx.x];
#pragma unroll
        for (int d = 4; d > 0; d >>= 1) s += __shfl_down_sync(0xffu, s, d);
        if (threadIdx.x == 0) g_part[blockIdx.x] = s;
    }
}

__global__ void k_scan2() {
    __shared__ int sp[256];
    int tid = threadIdx.x;
    int v = (tid < SCAN_BLOCKS) ? g_part[tid] : 0;
    sp[tid] = v;
    __syncthreads();
#pragma unroll
    for (int d = 1; d < 256; d <<= 1) {
        int u = (tid >= d) ? sp[tid - d] : 0;
        __syncthreads();
        sp[tid] += u;
        __syncthreads();
    }
    if (tid < SCAN_BLOCKS) g_part[tid] = (tid == 0) ? 0 : sp[tid - 1];
    if (tid == 255) g_off[N_NODES] = sp[255];
}

__global__ void k_scan3() {
    __shared__ int sv[256];
    int tid = threadIdx.x;
    int i = blockIdx.x * 256 + tid;
    int v = (i < N_NODES) ? g_deg[i] : 0;
    sv[tid] = v;
    __syncthreads();
#pragma unroll
    for (int d = 1; d < 256; d <<= 1) {
        int u = (tid >= d) ? sv[tid - d] : 0;
        __syncthreads();
        sv[tid] += u;
        __syncthreads();
    }
    if (i < N_NODES) {
        int excl = g_part[blockIdx.x] + sv[tid] - v;
        g_off[i] = excl;
        g_cur[i] = excl;
    }
}

// ---------------------------------------------------------------------------
__global__ void k_scatter(const void* __restrict__ ei) {
    int e = blockIdx.x * blockDim.x + threadIdx.x;
    if (e < N_EDGES) {
        int r = load_edge(ei, e);
        int c = load_edge(ei, (long long)e + N_EDGES);
        if (r >= 0 && r < N_NODES && c >= 0 && c < N_NODES) {
            int p = atomicAdd(&g_cur[r], 1);
            g_scol[p] = c;
        }
    }
}

// ---------------------------------------------------------------------------
// K5: warp-per-node segmented sum over CSR (fp16 x_t, fp32 accum) + tanh.
__global__ void k_gather(float* __restrict__ out) {
    int gw   = (blockIdx.x * blockDim.x + threadIdx.x) >> 5;
    int lane = threadIdx.x & 31;
    if (gw >= N_NODES) return;

    int s = g_off[gw];
    int e = g_off[gw + 1];
    const uint2* xt2 = (const uint2*)g_xt;

    float4 accA = make_float4(0.f, 0.f, 0.f, 0.f);
    float4 accB = make_float4(0.f, 0.f, 0.f, 0.f);

    int i = s;
    for (; i + 3 < e; i += 4) {
        int c0 = __ldg(&g_scol[i]);
        int c1 = __ldg(&g_scol[i + 1]);
        int c2 = __ldg(&g_scol[i + 2]);
        int c3 = __ldg(&g_scol[i + 3]);
        uint2 r0 = __ldg(&xt2[(size_t)c0 * 32 + lane]);
        uint2 r1 = __ldg(&xt2[(size_t)c1 * 32 + lane]);
        uint2 r2 = __ldg(&xt2[(size_t)c2 * 32 + lane]);
        uint2 r3 = __ldg(&xt2[(size_t)c3 * 32 + lane]);
        float2 a0 = __half22float2(*(const __half2*)&r0.x);
        float2 a1 = __half22float2(*(const __half2*)&r0.y);
        float2 b0 = __half22float2(*(const __half2*)&r1.x);
        float2 b1 = __half22float2(*(const __half2*)&r1.y);
        accA.x += a0.x; accA.y += a0.y; accA.z += a1.x; accA.w += a1.y;
        accB.x += b0.x; accB.y += b0.y; accB.z += b1.x; accB.w += b1.y;
        float2 d0 = __half22float2(*(const __half2*)&r2.x);
        float2 d1 = __half22float2(*(const __half2*)&r2.y);
        float2 e0 = __half22float2(*(const __half2*)&r3.x);
        float2 e1 = __half22float2(*(const __half2*)&r3.y);
        accA.x += d0.x; accA.y += d0.y; accA.z += d1.x; accA.w += d1.y;
        accB.x += e0.x; accB.y += e0.y; accB.z += e1.x; accB.w += e1.y;
    }
    for (; i < e; i++) {
        int c = __ldg(&g_scol[i]);
        uint2 r = __ldg(&xt2[(size_t)c * 32 + lane]);
        float2 p0 = __half22float2(*(const __half2*)&r.x);
        float2 p1 = __half22float2(*(const __half2*)&r.y);
        accA.x += p0.x; accA.y += p0.y; accA.z += p1.x; accA.w += p1.y;
    }

    float4 r = make_float4(tanhf(accA.x + accB.x), tanhf(accA.y + accB.y),
                           tanhf(accA.z + accB.z), tanhf(accA.w + accB.w));
    ((float4*)out)[(size_t)gw * 32 + lane] = r;
}

// ---------------------------------------------------------------------------
extern "C" void kernel_launch(void* const* d_in, const int* in_sizes, int n_in,
                              void* d_out, int out_size) {
    const float* x  = (const float*)d_in[0];
    const void*  ei = d_in[1];
    const float* W  = (const float*)d_in[2];
    const float* b  = (const float*)d_in[3];
    float*       out = (float*)d_out;

    // One-time side stream + events (host objects; created on the first,
    // non-captured, call; identical captured work every call).
    static cudaStream_t s1 = nullptr;
    static cudaEvent_t  evFork = nullptr, evJoin = nullptr;
    if (!s1) {
        cudaStreamCreateWithFlags(&s1, cudaStreamNonBlocking);
        cudaEventCreateWithFlags(&evFork, cudaEventDisableTiming);
        cudaEventCreateWithFlags(&evJoin, cudaEventDisableTiming);
    }

    k_detect<<<1, 32>>>(ei);                      // launch 1
    k_zero<<<(N_NODES + 255) / 256, 256>>>();     // launch 2

    // Fork: CSR build chain on s1, linear on main stream (overlapped).
    cudaEventRecord(evFork, 0);
    cudaStreamWaitEvent(s1, evFork, 0);

    k_count<<<(N_EDGES + 255) / 256, 256, 0, s1>>>(ei);   // launch 3

    dim3 lgrid((N_NODES + 63) / 64, 2);
    k_linear<<<lgrid, 128>>>(x, W, b);                    // launch 4 (profiled)

    k_scan1<<<SCAN_BLOCKS, 256, 0, s1>>>();
    k_scan2<<<1, 256, 0, s1>>>();
    k_scan3<<<SCAN_BLOCKS, 256, 0, s1>>>();
    k_scatter<<<(N_EDGES + 255) / 256, 256, 0, s1>>>(ei);

    // Join: gather needs CSR (s1) + x_t (main).
    cudaEventRecord(evJoin, s1);
    cudaStreamWaitEvent(0, evJoin, 0);

    k_gather<<<(N_NODES * 32 + 255) / 256, 256>>>(out);
}

// round 9
// speedup vs baseline: 3.0595x; 1.0267x over previous
#include <cuda_runtime.h>
#include <cuda_fp16.h>

#define N_NODES 50000
#define N_PAD   50048            // padded for tile-overrun reads
#define N_EDGES 800000
#define CIN 128
#define COUT 128

#define SCAN_BLOCKS ((N_NODES + 255) / 256)   // 196

// Scratch (allocation-free: __device__ globals)
__device__ int    g_is64;
__device__ int    g_deg[N_NODES];
__device__ int    g_off[N_NODES + 1];
__device__ int    g_cur[N_NODES];
__device__ int    g_part[SCAN_BLOCKS];
__device__ int    g_scol[N_EDGES];
__device__ __half g_xh[(size_t)N_PAD * CIN];      // fp16 input features
__device__ __half g_Wh[COUT * CIN];               // fp16 W [n][k]
__device__ __half g_xt[(size_t)N_NODES * COUT];   // fp16 transformed features

// ---------------------------------------------------------------------------
__device__ __forceinline__ void ldsm_x4(unsigned* r, unsigned addr) {
    asm volatile("ldmatrix.sync.aligned.m8n8.x4.shared.b16 {%0,%1,%2,%3}, [%4];"
                 : "=r"(r[0]), "=r"(r[1]), "=r"(r[2]), "=r"(r[3]) : "r"(addr));
}
__device__ __forceinline__ void mma16816(float* c, const unsigned* a, const unsigned* b) {
    asm volatile(
        "mma.sync.aligned.m16n8k16.row.col.f32.f16.f16.f32 "
        "{%0,%1,%2,%3}, {%4,%5,%6,%7}, {%8,%9}, {%0,%1,%2,%3};"
        : "+f"(c[0]), "+f"(c[1]), "+f"(c[2]), "+f"(c[3])
        : "r"(a[0]), "r"(a[1]), "r"(a[2]), "r"(a[3]), "r"(b[0]), "r"(b[1]));
}
__device__ __forceinline__ void cp16(unsigned dst, const void* src) {
    asm volatile("cp.async.cg.shared.global [%0], [%1], 16;" :: "r"(dst), "l"(src));
}

// ---------------------------------------------------------------------------
// KD: detect edge_index dtype — parallel.
__global__ void k_detect(const void* ei_raw) {
    const long long* p = (const long long*)ei_raw;
    int lane = threadIdx.x;
    long long v0 = p[lane];
    long long v1 = p[lane + 32];
    int bad = (v0 < 0 || v0 >= N_NODES || v1 < 0 || v1 >= N_NODES);
    unsigned m = __ballot_sync(0xffffffffu, bad);
    if (lane == 0) g_is64 = (m == 0);
}

__device__ __forceinline__ int load_edge(const void* ei_raw, long long idx) {
    if (g_is64) return (int)((const long long*)ei_raw)[idx];
    return ((const int*)ei_raw)[idx];
}

// ---------------------------------------------------------------------------
// KX: x fp32 -> g_xh fp16 (padding rows zeroed).
__global__ void k_xconv(const float* __restrict__ x) {
    int i = blockIdx.x * blockDim.x + threadIdx.x;      // float4 index
    const int TOT4 = N_PAD * CIN / 4;                   // 1,601,536
    if (i >= TOT4) return;
    const int REAL4 = N_NODES * CIN / 4;
    float4 v = (i < REAL4) ? ((const float4*)x)[i] : make_float4(0.f, 0.f, 0.f, 0.f);
    __half2 h0 = __floats2half2_rn(v.x, v.y);
    __half2 h1 = __floats2half2_rn(v.z, v.w);
    uint2 st = { *(unsigned*)&h0, *(unsigned*)&h1 };
    ((uint2*)g_xh)[i] = st;
}

// KW: W fp32 -> g_Wh fp16 (same [n][k] layout).
__global__ void k_wt(const float* __restrict__ W) {
    int i = blockIdx.x * blockDim.x + threadIdx.x;      // float4 index, 4096 total
    if (i >= COUT * CIN / 4) return;
    float4 v = ((const float4*)W)[i];
    __half2 h0 = __floats2half2_rn(v.x, v.y);
    __half2 h1 = __floats2half2_rn(v.z, v.w);
    uint2 st = { *(unsigned*)&h0, *(unsigned*)&h1 };
    ((uint2*)g_Wh)[i] = st;
}

// ---------------------------------------------------------------------------
__global__ void k_zero() {
    int i = blockIdx.x * blockDim.x + threadIdx.x;
    if (i < N_NODES) g_deg[i] = 0;
}

__global__ void k_count(const void* __restrict__ ei) {
    int e = blockIdx.x * blockDim.x + threadIdx.x;
    if (e < N_EDGES) {
        int r = load_edge(ei, e);
        if (r >= 0 && r < N_NODES) atomicAdd(&g_deg[r], 1);
    }
}

// ---------------------------------------------------------------------------
// K4: x_t = x @ W^T + b via HMMA. Block = 64 nodes x 128 oc, 256 thr.
// Fills via cp.async from preconverted fp16. Dynamic smem 52.2KB.
#define LSTRIDE 136
#define A_HALVES (64 * LSTRIDE)
__global__ void __launch_bounds__(256) k_linear(const float* __restrict__ b) {
    extern __shared__ __align__(16) __half sm[];
    __half* As = sm;                  // [64][LSTRIDE]
    __half* Bs = sm + A_HALVES;       // [128][LSTRIDE]

    int tid = threadIdx.x, lane = tid & 31, warp = tid >> 5;
    int wm = warp & 3;                // node slice (16 rows)
    int wn = warp >> 2;               // oc half (64 cols)
    int m0 = blockIdx.x * 64;

    unsigned a_base = (unsigned)__cvta_generic_to_shared(As);
    unsigned b_base = (unsigned)__cvta_generic_to_shared(Bs);

    // A fill: 64 rows x 16 chunks of 16B. 1024 chunks, 4/thread.
    for (int c = tid; c < 64 * 16; c += 256) {
        int row = c >> 4, col = c & 15;
        cp16(a_base + row * (LSTRIDE * 2) + col * 16,
             &g_xh[(size_t)(m0 + row) * CIN + col * 8]);
    }
    // B fill: 128 rows x 16 chunks. 2048 chunks, 8/thread.
    for (int c = tid; c < 128 * 16; c += 256) {
        int row = c >> 4, col = c & 15;
        cp16(b_base + row * (LSTRIDE * 2) + col * 16,
             &g_Wh[row * CIN + col * 8]);
    }
    asm volatile("cp.async.commit_group;");
    asm volatile("cp.async.wait_group 0;" ::: "memory");
    __syncthreads();

    float acc[8][4];
#pragma unroll
    for (int i = 0; i < 8; i++)
#pragma unroll
        for (int j = 0; j < 4; j++) acc[i][j] = 0.f;

    int m_warp = wm * 16;
    unsigned a_off = a_base + ((m_warp + (lane & 15)) * LSTRIDE + (lane >> 4) * 8) * 2;
    unsigned b_off = b_base + (wn * 64 + ((lane >> 4) << 3) + (lane & 7)) * (LSTRIDE * 2)
                            + (((lane >> 3) & 1) * 8) * 2;

#pragma unroll
    for (int kk = 0; kk < 8; kk++) {
        unsigned a[4];
        ldsm_x4(a, a_off + kk * 32);
#pragma unroll
        for (int ntp = 0; ntp < 4; ntp++) {
            unsigned bf[4];
            ldsm_x4(bf, b_off + (ntp * 16 * LSTRIDE) * 2 + kk * 32);
            mma16816(acc[ntp * 2],     a, bf);
            mma16816(acc[ntp * 2 + 1], a, bf + 2);
        }
    }

    int row0 = m_warp + (lane >> 2);
#pragma unroll
    for (int nt = 0; nt < 8; nt++) {
        int col = wn * 64 + nt * 8 + (lane & 3) * 2;
        float2 bv = *(const float2*)&b[col];
        int na = m0 + row0;
        if (na < N_NODES) {
            __half2 h = __floats2half2_rn(acc[nt][0] + bv.x, acc[nt][1] + bv.y);
            *(__half2*)&g_xt[(size_t)na * COUT + col] = h;
        }
        int nb = na + 8;
        if (nb < N_NODES) {
            __half2 h = __floats2half2_rn(acc[nt][2] + bv.x, acc[nt][3] + bv.y);
            *(__half2*)&g_xt[(size_t)nb * COUT + col] = h;
        }
    }
}

// ---------------------------------------------------------------------------
// Multi-block exclusive scan of g_deg -> g_off / g_cur.
__global__ void k_scan1() {
    __shared__ int warpsum[8];
    int i = blockIdx.x * 256 + threadIdx.x;
    int v = (i < N_NODES) ? g_deg[i] : 0;
#pragma unroll
    for (int d = 16; d > 0; d >>= 1) v += __shfl_down_sync(0xffffffffu, v, d);
    if ((threadIdx.x & 31) == 0) warpsum[threadIdx.x >> 5] = v;
    __syncthreads();
    if (threadIdx.x < 8) {
        int s = warpsum[threadIdx.x];
#pragma unroll
        for (int d = 4; d > 0; d >>= 1) s += __shfl_down_sync(0xffu, s, d);
        if (threadIdx.x == 0) g_part[blockIdx.x] = s;
    }
}

__global__ void k_scan2() {
    __shared__ int sp[256];
    int tid = threadIdx.x;
    int v = (tid < SCAN_BLOCKS) ? g_part[tid] : 0;
    sp[tid] = v;
    __syncthreads();
#pragma unroll
    for (int d = 1; d < 256; d <<= 1) {
        int u = (tid >= d) ? sp[tid - d] : 0;
        __syncthreads();
        sp[tid] += u;
        __syncthreads();
    }
    if (tid < SCAN_BLOCKS) g_part[tid] = (tid == 0) ? 0 : sp[tid - 1];
    if (tid == 255) g_off[N_NODES] = sp[255];
}

__global__ void k_scan3() {
    __shared__ int sv[256];
    int tid = threadIdx.x;
    int i = blockIdx.x * 256 + tid;
    int v = (i < N_NODES) ? g_deg[i] : 0;
    sv[tid] = v;
    __syncthreads();
#pragma unroll
    for (int d = 1; d < 256; d <<= 1) {
        int u = (tid >= d) ? sv[tid - d] : 0;
        __syncthreads();
        sv[tid] += u;
        __syncthreads();
    }
    if (i < N_NODES) {
        int excl = g_part[blockIdx.x] + sv[tid] - v;
        g_off[i] = excl;
        g_cur[i] = excl;
    }
}

// ---------------------------------------------------------------------------
__global__ void k_scatter(const void* __restrict__ ei) {
    int e = blockIdx.x * blockDim.x + threadIdx.x;
    if (e < N_EDGES) {
        int r = load_edge(ei, e);
        int c = load_edge(ei, (long long)e + N_EDGES);
        if (r >= 0 && r < N_NODES && c >= 0 && c < N_NODES) {
            int p = atomicAdd(&g_cur[r], 1);
            g_scol[p] = c;
        }
    }
}

// ---------------------------------------------------------------------------
// K5: warp-per-node segmented sum over CSR (fp16 x_t, fp32 accum) + tanh.
__global__ void k_gather(float* __restrict__ out) {
    int gw   = (blockIdx.x * blockDim.x + threadIdx.x) >> 5;
    int lane = threadIdx.x & 31;
    if (gw >= N_NODES) return;

    int s = g_off[gw];
    int e = g_off[gw + 1];
    const uint2* xt2 = (const uint2*)g_xt;

    float4 accA = make_float4(0.f, 0.f, 0.f, 0.f);
    float4 accB = make_float4(0.f, 0.f, 0.f, 0.f);

    int i = s;
    for (; i + 3 < e; i += 4) {
        int c0 = __ldg(&g_scol[i]);
        int c1 = __ldg(&g_scol[i + 1]);
        int c2 = __ldg(&g_scol[i + 2]);
        int c3 = __ldg(&g_scol[i + 3]);
        uint2 r0 = __ldg(&xt2[(size_t)c0 * 32 + lane]);
        uint2 r1 = __ldg(&xt2[(size_t)c1 * 32 + lane]);
        uint2 r2 = __ldg(&xt2[(size_t)c2 * 32 + lane]);
        uint2 r3 = __ldg(&xt2[(size_t)c3 * 32 + lane]);
        float2 a0 = __half22float2(*(const __half2*)&r0.x);
        float2 a1 = __half22float2(*(const __half2*)&r0.y);
        float2 b0 = __half22float2(*(const __half2*)&r1.x);
        float2 b1 = __half22float2(*(const __half2*)&r1.y);
        accA.x += a0.x; accA.y += a0.y; accA.z += a1.x; accA.w += a1.y;
        accB.x += b0.x; accB.y += b0.y; accB.z += b1.x; accB.w += b1.y;
        float2 d0 = __half22float2(*(const __half2*)&r2.x);
        float2 d1 = __half22float2(*(const __half2*)&r2.y);
        float2 e0 = __half22float2(*(const __half2*)&r3.x);
        float2 e1 = __half22float2(*(const __half2*)&r3.y);
        accA.x += d0.x; accA.y += d0.y; accA.z += d1.x; accA.w += d1.y;
        accB.x += e0.x; accB.y += e0.y; accB.z += e1.x; accB.w += e1.y;
    }
    for (; i < e; i++) {
        int c = __ldg(&g_scol[i]);
        uint2 r = __ldg(&xt2[(size_t)c * 32 + lane]);
        float2 p0 = __half22float2(*(const __half2*)&r.x);
        float2 p1 = __half22float2(*(const __half2*)&r.y);
        accA.x += p0.x; accA.y += p0.y; accA.z += p1.x; accA.w += p1.y;
    }

    float4 r = make_float4(tanhf(accA.x + accB.x), tanhf(accA.y + accB.y),
                           tanhf(accA.z + accB.z), tanhf(accA.w + accB.w));
    ((float4*)out)[(size_t)gw * 32 + lane] = r;
}

// ---------------------------------------------------------------------------
extern "C" void kernel_launch(void* const* d_in, const int* in_sizes, int n_in,
                              void* d_out, int out_size) {
    const float* x  = (const float*)d_in[0];
    const void*  ei = d_in[1];
    const float* W  = (const float*)d_in[2];
    const float* b  = (const float*)d_in[3];
    float*       out = (float*)d_out;

    static cudaStream_t s1 = nullptr;
    static cudaEvent_t  evFork = nullptr, evJoin = nullptr;
    if (!s1) {
        cudaStreamCreateWithFlags(&s1, cudaStreamNonBlocking);
        cudaEventCreateWithFlags(&evFork, cudaEventDisableTiming);
        cudaEventCreateWithFlags(&evJoin, cudaEventDisableTiming);
        cudaFuncSetAttribute(k_linear, cudaFuncAttributeMaxDynamicSharedMemorySize,
                             (A_HALVES + 128 * LSTRIDE) * 2);
    }
    const int SMEM_LIN = (A_HALVES + 128 * LSTRIDE) * 2;   // 52.2 KB

    // Main stream: detect -> xconv/wt -> linear (launches 1-4; slot 4 profiled)
    k_detect<<<1, 32>>>(ei);
    cudaEventRecord(evFork, 0);

    k_xconv<<<(N_PAD * CIN / 4 + 255) / 256, 256>>>(x);
    k_wt<<<16, 256>>>(W);
    k_linear<<<(N_NODES + 63) / 64, 256, SMEM_LIN>>>(b);

    // Side stream: CSR build (overlaps the linear chain).
    cudaStreamWaitEvent(s1, evFork, 0);
    k_zero<<<(N_NODES + 255) / 256, 256, 0, s1>>>();
    k_count<<<(N_EDGES + 255) / 256, 256, 0, s1>>>(ei);
    k_scan1<<<SCAN_BLOCKS, 256, 0, s1>>>();
    k_scan2<<<1, 256, 0, s1>>>();
    k_scan3<<<SCAN_BLOCKS, 256, 0, s1>>>();
    k_scatter<<<(N_EDGES + 255) / 256, 256, 0, s1>>>(ei);

    cudaEventRecord(evJoin, s1);
    cudaStreamWaitEvent(0, evJoin, 0);

    k_gather<<<(N_NODES * 32 + 255) / 256, 256>>>(out);
}